// round 3
// baseline (speedup 1.0000x reference)
#include <cuda_runtime.h>
#include <math.h>

#define NHEADS 16
#define DKH 64
#define BATCH 2
#define SEQ 2048
#define DMODEL 1024
#define MTOT (BATCH * SEQ)      // 4096
#define BHTOT (BATCH * NHEADS)  // 32

// Scratch (__device__ globals: allocation-free)
__device__ float g_q[BHTOT * SEQ * DKH];
__device__ float g_k[BHTOT * SEQ * DKH];
__device__ float g_v[BHTOT * SEQ * DKH];
__device__ float g_attn[MTOT * DMODEL];

// ============================================================
// SGEMM: C = A (M x K) * B (N x K)^T, M=4096, N=1024, K=1024
// DEST 0/1/2: A=arg,   C=g_q/g_k/g_v (split-heads epilogue)
// DEST 3:     A=g_attn, C=arg (plain row-major, final output)
// BM=BN=128, BK=8, 256 threads, 8x8 micro-tile per thread
// ============================================================
template <int DEST>
__global__ __launch_bounds__(256, 2) void sgemm_nt(const float* __restrict__ Ain,
                                                   const float* __restrict__ Bw,
                                                   float* __restrict__ Cout) {
    const int K = 1024;
    __shared__ __align__(16) float As[8 * 128];
    __shared__ __align__(16) float Bs[8 * 128];

    const float* A = (DEST == 3) ? (const float*)g_attn : Ain;

    const int tid = threadIdx.x;
    const int bm = blockIdx.y, bn = blockIdx.x;
    const int lrow = tid >> 1;           // 0..127
    const int kcol = (tid & 1) * 4;      // 0 or 4
    const int ty = tid >> 4;             // 0..15
    const int tx = tid & 15;             // 0..15

    const float* Aptr = A + (bm * 128 + lrow) * K + kcol;
    const float* Bptr = Bw + (bn * 128 + lrow) * K + kcol;

    float acc[8][8];
#pragma unroll
    for (int i = 0; i < 8; i++)
#pragma unroll
        for (int j = 0; j < 8; j++) acc[i][j] = 0.0f;

    float4 a = *(const float4*)(Aptr);
    float4 b = *(const float4*)(Bptr);

    for (int k0 = 0; k0 < K; k0 += 8) {
        As[(kcol + 0) * 128 + lrow] = a.x;
        As[(kcol + 1) * 128 + lrow] = a.y;
        As[(kcol + 2) * 128 + lrow] = a.z;
        As[(kcol + 3) * 128 + lrow] = a.w;
        Bs[(kcol + 0) * 128 + lrow] = b.x;
        Bs[(kcol + 1) * 128 + lrow] = b.y;
        Bs[(kcol + 2) * 128 + lrow] = b.z;
        Bs[(kcol + 3) * 128 + lrow] = b.w;
        __syncthreads();

        if (k0 + 8 < K) {
            a = *(const float4*)(Aptr + k0 + 8);
            b = *(const float4*)(Bptr + k0 + 8);
        }

#pragma unroll
        for (int kk = 0; kk < 8; kk++) {
            float4 a0 = *(const float4*)&As[kk * 128 + ty * 8];
            float4 a1 = *(const float4*)&As[kk * 128 + ty * 8 + 4];
            float4 b0 = *(const float4*)&Bs[kk * 128 + tx * 8];
            float4 b1 = *(const float4*)&Bs[kk * 128 + tx * 8 + 4];
            float ra[8] = {a0.x, a0.y, a0.z, a0.w, a1.x, a1.y, a1.z, a1.w};
            float rb[8] = {b0.x, b0.y, b0.z, b0.w, b1.x, b1.y, b1.z, b1.w};
#pragma unroll
            for (int i = 0; i < 8; i++)
#pragma unroll
                for (int j = 0; j < 8; j++) acc[i][j] += ra[i] * rb[j];
        }
        __syncthreads();
    }

    float* C;
    if (DEST == 0) C = g_q;
    else if (DEST == 1) C = g_k;
    else if (DEST == 2) C = g_v;
    else C = Cout;

#pragma unroll
    for (int i = 0; i < 8; i++) {
        const int m = bm * 128 + ty * 8 + i;
#pragma unroll
        for (int j = 0; j < 8; j++) {
            const int n = bn * 128 + tx * 8 + j;
            if (DEST == 3) {
                C[m * 1024 + n] = acc[i][j];
            } else {
                // split heads: m=b*2048+l, n=h*64+dk -> [((b*16+h)*2048+l)*64+dk]
                const int bb = m >> 11, ll = m & 2047;
                const int hh = n >> 6, dk = n & 63;
                C[(((bb * 16 + hh) * 2048) + ll) * 64 + dk] = acc[i][j];
            }
        }
    }
}

// ============================================================
// Causal flash attention, fp32. BR=64, BC=32, dk=64.
// Grid: (SEQ/64, B*H). 256 threads = 8 warps; warp w owns rows w*8..w*8+7;
// lane owns S-col `lane` (of 32), O-dims {lane, lane+32}.
// Pitch 68 floats: 16B-aligned float4 rows AND conflict-free LDS
// (stride 272B -> lane l hits banks {4l..4l+3} mod 32, all distinct).
// Static smem 43.3KB < 48KB: no cudaFuncSetAttribute needed.
// ============================================================
#define QP 68   // pitch for 64-wide rows (multiple of 4!)
#define PP 33   // pitch for 32-wide P rows (scalar access only)

__global__ __launch_bounds__(256) void flash_attn() {
    __shared__ __align__(16) float Qs[64 * QP];
    __shared__ __align__(16) float Ks[32 * QP];
    __shared__ __align__(16) float Vs[32 * QP];
    __shared__ __align__(16) float Ps[64 * PP];

    const int bh = blockIdx.y;
    const int rb = blockIdx.x;
    const int tid = threadIdx.x;
    const int lane = tid & 31;
    const int warp = tid >> 5;

    // Load Q tile: 64 rows x 64 floats = 1024 float4 slots, 256 threads x 4
    const float* qbase = g_q + ((size_t)bh * SEQ + rb * 64) * DKH;
#pragma unroll
    for (int i = 0; i < 4; i++) {
        int e = tid + i * 256;       // float4 slot 0..1023
        int r = e >> 4, d4 = (e & 15) * 4;
        float4 v = *(const float4*)(qbase + r * DKH + d4);
        *(float4*)&Qs[r * QP + d4] = v;
    }

    float m_i[8], l_i[8], o0[8], o1[8];
#pragma unroll
    for (int r = 0; r < 8; r++) {
        m_i[r] = -INFINITY;
        l_i[r] = 0.0f;
        o0[r] = 0.0f;
        o1[r] = 0.0f;
    }

    const float scale = 0.125f;  // 1/sqrt(64)
    const int tmax = 2 * rb + 1; // 32-col tiles covering cols <= rb*64+63

    for (int t = 0; t <= tmax; t++) {
        __syncthreads();  // prior tile's Ks/Vs fully consumed (also covers Q load)
        // Load K,V tile: 32 rows x 64 = 512 float4 slots each; 256 threads x 2
        const float* kb = g_k + ((size_t)bh * SEQ + t * 32) * DKH;
        const float* vb = g_v + ((size_t)bh * SEQ + t * 32) * DKH;
#pragma unroll
        for (int i = 0; i < 2; i++) {
            int e = tid + i * 256;   // 0..511
            int r = e >> 4, d4 = (e & 15) * 4;
            float4 kv = *(const float4*)(kb + r * DKH + d4);
            float4 vv = *(const float4*)(vb + r * DKH + d4);
            *(float4*)&Ks[r * QP + d4] = kv;
            *(float4*)&Vs[r * QP + d4] = vv;
        }
        __syncthreads();

        // S = Q K^T for this warp's 8 rows, 1 col (lane) per lane
        float s[8];
#pragma unroll
        for (int r = 0; r < 8; r++) s[r] = 0.0f;
#pragma unroll
        for (int d4 = 0; d4 < 16; d4++) {
            float4 kq = *(const float4*)&Ks[lane * QP + d4 * 4];
#pragma unroll
            for (int r = 0; r < 8; r++) {
                float4 qq = *(const float4*)&Qs[(warp * 8 + r) * QP + d4 * 4];
                s[r] += qq.x * kq.x + qq.y * kq.y + qq.z * kq.z + qq.w * kq.w;
            }
        }

        const bool masked = (t >= 2 * rb);  // tile touches/crosses diagonal
        const int col = t * 32 + lane;
#pragma unroll
        for (int r = 0; r < 8; r++) {
            const int rr = warp * 8 + r;
            const int grow = rb * 64 + rr;
            float v0 = s[r] * scale;
            if (masked && col > grow) v0 = -INFINITY;
            float mx = v0;
#pragma unroll
            for (int off = 16; off > 0; off >>= 1)
                mx = fmaxf(mx, __shfl_xor_sync(0xFFFFFFFFu, mx, off));
            const float mnew = fmaxf(m_i[r], mx);
            const float scl = __expf(m_i[r] - mnew);
            const float p0 = __expf(v0 - mnew);
            float rs = p0;
#pragma unroll
            for (int off = 16; off > 0; off >>= 1)
                rs += __shfl_xor_sync(0xFFFFFFFFu, rs, off);
            l_i[r] = l_i[r] * scl + rs;
            m_i[r] = mnew;
            o0[r] *= scl;
            o1[r] *= scl;
            Ps[rr * PP + lane] = p0;
        }
        __syncwarp();

        // O += P V  (lane owns dims lane, lane+32), P rows are warp-private
#pragma unroll 8
        for (int c = 0; c < 32; c++) {
            float vv0 = Vs[c * QP + lane];
            float vv1 = Vs[c * QP + lane + 32];
#pragma unroll
            for (int r = 0; r < 8; r++) {
                float p = Ps[(warp * 8 + r) * PP + c];
                o0[r] += p * vv0;
                o1[r] += p * vv1;
            }
        }
        __syncwarp();
    }

    // Write merged-head layout: (b, l, h*64+dk)
    const int bb = bh >> 4, hh = bh & 15;
#pragma unroll
    for (int r = 0; r < 8; r++) {
        const int rr = warp * 8 + r;
        const int grow = rb * 64 + rr;
        const float inv = 1.0f / l_i[r];
        float* dst = g_attn + ((size_t)(bb * SEQ + grow)) * DMODEL + hh * 64;
        dst[lane] = o0[r] * inv;
        dst[lane + 32] = o1[r] * inv;
    }
}

// ============================================================
// Launch: kernel launches ONLY (graph-capture-safe, no runtime API,
// no static state, no symbol-address lookups)
// ============================================================
extern "C" void kernel_launch(void* const* d_in, const int* in_sizes, int n_in,
                              void* d_out, int out_size) {
    const float* x = (const float*)d_in[0];
    const float* wq = (const float*)d_in[1];
    const float* wk = (const float*)d_in[2];
    const float* wv = (const float*)d_in[3];
    const float* wo = (const float*)d_in[4];
    float* out = (float*)d_out;

    dim3 gemm_grid(DMODEL / 128, MTOT / 128);  // (8, 32)
    sgemm_nt<0><<<gemm_grid, 256>>>(x, wq, nullptr);
    sgemm_nt<1><<<gemm_grid, 256>>>(x, wk, nullptr);
    sgemm_nt<2><<<gemm_grid, 256>>>(x, wv, nullptr);

    dim3 attn_grid(SEQ / 64, BHTOT);  // (32, 32)
    flash_attn<<<attn_grid, 256>>>();

    sgemm_nt<3><<<gemm_grid, 256>>>(nullptr, wo, out);
}

// round 5
// speedup vs baseline: 1.2141x; 1.2141x over previous
#include <cuda_runtime.h>
#include <math.h>
#include <stdint.h>

#define NHEADS 16
#define DKH 64
#define BATCH 2
#define SEQ 2048
#define DMODEL 1024
#define MTOT (BATCH * SEQ)      // 4096
#define BHTOT (BATCH * NHEADS)  // 32

// Scratch (__device__ globals: allocation-free)
__device__ float g_q[BHTOT * SEQ * DKH];
__device__ float g_k[BHTOT * SEQ * DKH];
__device__ float g_v[BHTOT * SEQ * DKH];
__device__ float g_attn[MTOT * DMODEL];

// ============================================================
// SIMT fp32 SGEMM (precision-critical Q,K projections only).
// C = A (M x K) * B (N x K)^T; DEST 0 -> g_q, 1 -> g_k (split heads)
// ============================================================
template <int DEST>
__global__ __launch_bounds__(256, 2) void sgemm_nt(const float* __restrict__ Ain,
                                                   const float* __restrict__ Bw) {
    const int K = 1024;
    __shared__ __align__(16) float As[8 * 128];
    __shared__ __align__(16) float Bs[8 * 128];

    const float* A = Ain;

    const int tid = threadIdx.x;
    const int bm = blockIdx.y, bn = blockIdx.x;
    const int lrow = tid >> 1;           // 0..127
    const int kcol = (tid & 1) * 4;      // 0 or 4
    const int ty = tid >> 4;             // 0..15
    const int tx = tid & 15;             // 0..15

    const float* Aptr = A + (bm * 128 + lrow) * K + kcol;
    const float* Bptr = Bw + (bn * 128 + lrow) * K + kcol;

    float acc[8][8];
#pragma unroll
    for (int i = 0; i < 8; i++)
#pragma unroll
        for (int j = 0; j < 8; j++) acc[i][j] = 0.0f;

    float4 a = *(const float4*)(Aptr);
    float4 b = *(const float4*)(Bptr);

    for (int k0 = 0; k0 < K; k0 += 8) {
        As[(kcol + 0) * 128 + lrow] = a.x;
        As[(kcol + 1) * 128 + lrow] = a.y;
        As[(kcol + 2) * 128 + lrow] = a.z;
        As[(kcol + 3) * 128 + lrow] = a.w;
        Bs[(kcol + 0) * 128 + lrow] = b.x;
        Bs[(kcol + 1) * 128 + lrow] = b.y;
        Bs[(kcol + 2) * 128 + lrow] = b.z;
        Bs[(kcol + 3) * 128 + lrow] = b.w;
        __syncthreads();

        if (k0 + 8 < K) {
            a = *(const float4*)(Aptr + k0 + 8);
            b = *(const float4*)(Bptr + k0 + 8);
        }

#pragma unroll
        for (int kk = 0; kk < 8; kk++) {
            float4 a0 = *(const float4*)&As[kk * 128 + ty * 8];
            float4 a1 = *(const float4*)&As[kk * 128 + ty * 8 + 4];
            float4 b0 = *(const float4*)&Bs[kk * 128 + tx * 8];
            float4 b1 = *(const float4*)&Bs[kk * 128 + tx * 8 + 4];
            float ra[8] = {a0.x, a0.y, a0.z, a0.w, a1.x, a1.y, a1.z, a1.w};
            float rb[8] = {b0.x, b0.y, b0.z, b0.w, b1.x, b1.y, b1.z, b1.w};
#pragma unroll
            for (int i = 0; i < 8; i++)
#pragma unroll
                for (int j = 0; j < 8; j++) acc[i][j] += ra[i] * rb[j];
        }
        __syncthreads();
    }

    float* C = (DEST == 0) ? g_q : g_k;

#pragma unroll
    for (int i = 0; i < 8; i++) {
        const int m = bm * 128 + ty * 8 + i;
#pragma unroll
        for (int j = 0; j < 8; j++) {
            const int n = bn * 128 + tx * 8 + j;
            // split heads: m=b*2048+l, n=h*64+dk -> [((b*16+h)*2048+l)*64+dk]
            const int bb = m >> 11, ll = m & 2047;
            const int hh = n >> 6, dk = n & 63;
            C[(((bb * 16 + hh) * 2048) + ll) * 64 + dk] = acc[i][j];
        }
    }
}

// ============================================================
// TF32 tensor-core GEMM (V-proj and O-proj: linear error path).
// C = A (M x K) * B (N x K)^T via mma.sync.m16n8k8 tf32,
// cvt.rna rounding at smem fill. BM=BN=128, BK=16, 8 warps (2x4),
// warp tile 64x32 (4 m-tiles x 4 n-tiles of 16x8).
// Smem pitch 20 words/row: frag-load bank = (20g+t)%32 = permutation.
// DEST 2: A=arg(x), C=g_v split-heads.  DEST 3: A=g_attn, C=arg.
// ============================================================
#define TP 20

__device__ __forceinline__ uint32_t f2tf32(float x) {
    uint32_t r;
    asm("cvt.rna.tf32.f32 %0, %1;" : "=r"(r) : "f"(x));
    return r;
}

__device__ __forceinline__ void mma_tf32(float d[4], const uint32_t a[4],
                                         const uint32_t b[2]) {
    asm volatile(
        "mma.sync.aligned.m16n8k8.row.col.f32.tf32.tf32.f32 "
        "{%0,%1,%2,%3}, {%4,%5,%6,%7}, {%8,%9}, {%0,%1,%2,%3};\n"
        : "+f"(d[0]), "+f"(d[1]), "+f"(d[2]), "+f"(d[3])
        : "r"(a[0]), "r"(a[1]), "r"(a[2]), "r"(a[3]), "r"(b[0]), "r"(b[1]));
}

template <int DEST>
__global__ __launch_bounds__(256, 2) void tf32_gemm(const float* __restrict__ Ain,
                                                    const float* __restrict__ Bw,
                                                    float* __restrict__ Cout) {
    __shared__ __align__(16) uint32_t As[128 * TP];
    __shared__ __align__(16) uint32_t Bs[128 * TP];

    const float* A = (DEST == 3) ? (const float*)g_attn : Ain;
    const int K = 1024;
    const int tid = threadIdx.x;
    const int lane = tid & 31, warp = tid >> 5;
    const int wm = warp >> 2, wn = warp & 3;  // 2 x 4 warp grid
    const int g = lane >> 2, t = lane & 3;    // groupID, thread-in-group
    const int bm = blockIdx.y, bn = blockIdx.x;

    const int lm = tid >> 2;          // 0..63 (row in tile; also +64)
    const int k4 = (tid & 3) * 4;     // 0,4,8,12

    const float* Ap = A + (size_t)(bm * 128 + lm) * K + k4;
    const float* Bp = Bw + (size_t)(bn * 128 + lm) * K + k4;

    float d[4][4][4];
#pragma unroll
    for (int i = 0; i < 4; i++)
#pragma unroll
        for (int j = 0; j < 4; j++)
#pragma unroll
            for (int c = 0; c < 4; c++) d[i][j][c] = 0.0f;

    float4 a0v = *(const float4*)(Ap);
    float4 a1v = *(const float4*)(Ap + 64 * K);
    float4 b0v = *(const float4*)(Bp);
    float4 b1v = *(const float4*)(Bp + 64 * K);

    for (int k0 = 0; k0 < K; k0 += 16) {
        uint4 s;
        s.x = f2tf32(a0v.x); s.y = f2tf32(a0v.y); s.z = f2tf32(a0v.z); s.w = f2tf32(a0v.w);
        *(uint4*)&As[lm * TP + k4] = s;
        s.x = f2tf32(a1v.x); s.y = f2tf32(a1v.y); s.z = f2tf32(a1v.z); s.w = f2tf32(a1v.w);
        *(uint4*)&As[(lm + 64) * TP + k4] = s;
        s.x = f2tf32(b0v.x); s.y = f2tf32(b0v.y); s.z = f2tf32(b0v.z); s.w = f2tf32(b0v.w);
        *(uint4*)&Bs[lm * TP + k4] = s;
        s.x = f2tf32(b1v.x); s.y = f2tf32(b1v.y); s.z = f2tf32(b1v.z); s.w = f2tf32(b1v.w);
        *(uint4*)&Bs[(lm + 64) * TP + k4] = s;
        __syncthreads();

        if (k0 + 16 < K) {
            a0v = *(const float4*)(Ap + k0 + 16);
            a1v = *(const float4*)(Ap + 64 * K + k0 + 16);
            b0v = *(const float4*)(Bp + k0 + 16);
            b1v = *(const float4*)(Bp + 64 * K + k0 + 16);
        }

#pragma unroll
        for (int ks = 0; ks < 16; ks += 8) {
            uint32_t af[4][4], bf[4][2];
#pragma unroll
            for (int mt = 0; mt < 4; mt++) {
                const int mb = wm * 64 + mt * 16 + g;
                af[mt][0] = As[mb * TP + ks + t];
                af[mt][1] = As[(mb + 8) * TP + ks + t];
                af[mt][2] = As[mb * TP + ks + t + 4];
                af[mt][3] = As[(mb + 8) * TP + ks + t + 4];
            }
#pragma unroll
            for (int nt = 0; nt < 4; nt++) {
                const int nb = wn * 32 + nt * 8 + g;
                bf[nt][0] = Bs[nb * TP + ks + t];
                bf[nt][1] = Bs[nb * TP + ks + t + 4];
            }
#pragma unroll
            for (int mt = 0; mt < 4; mt++)
#pragma unroll
                for (int nt = 0; nt < 4; nt++) mma_tf32(d[mt][nt], af[mt], bf[nt]);
        }
        __syncthreads();
    }

    // Epilogue: c0,c1 at (row, 2t..2t+1); c2,c3 at (row+8, same cols)
#pragma unroll
    for (int mt = 0; mt < 4; mt++) {
#pragma unroll
        for (int nt = 0; nt < 4; nt++) {
            const int m0 = bm * 128 + wm * 64 + mt * 16 + g;
            const int n0 = bn * 128 + wn * 32 + nt * 8 + 2 * t;
#pragma unroll
            for (int half = 0; half < 2; half++) {
                const int m = m0 + half * 8;
                const float v0 = d[mt][nt][half * 2 + 0];
                const float v1 = d[mt][nt][half * 2 + 1];
                if (DEST == 3) {
                    float2* p = (float2*)&Cout[(size_t)m * 1024 + n0];
                    *p = make_float2(v0, v1);
                } else {
                    // split heads into g_v
                    const int bb = m >> 11, ll = m & 2047;
                    const int hh = n0 >> 6, dk = n0 & 63;
                    float2* p = (float2*)&g_v[(((size_t)(bb * 16 + hh) * 2048) + ll) * 64 + dk];
                    *p = make_float2(v0, v1);
                }
            }
        }
    }
}

// ============================================================
// Causal flash attention, fp32. BR=64, BC=32, dk=64.
// occ bump: launch_bounds(256,3) (was reg-limited at 2 CTA/SM)
// ============================================================
#define QP 68   // pitch for 64-wide rows (multiple of 4: aligned float4)
#define PP 33   // pitch for 32-wide P rows (scalar access only)

__global__ __launch_bounds__(256, 3) void flash_attn() {
    __shared__ __align__(16) float Qs[64 * QP];
    __shared__ __align__(16) float Ks[32 * QP];
    __shared__ __align__(16) float Vs[32 * QP];
    __shared__ __align__(16) float Ps[64 * PP];

    const int bh = blockIdx.y;
    const int rb = blockIdx.x;
    const int tid = threadIdx.x;
    const int lane = tid & 31;
    const int warp = tid >> 5;

    const float* qbase = g_q + ((size_t)bh * SEQ + rb * 64) * DKH;
#pragma unroll
    for (int i = 0; i < 4; i++) {
        int e = tid + i * 256;
        int r = e >> 4, d4 = (e & 15) * 4;
        float4 v = *(const float4*)(qbase + r * DKH + d4);
        *(float4*)&Qs[r * QP + d4] = v;
    }

    float m_i[8], l_i[8], o0[8], o1[8];
#pragma unroll
    for (int r = 0; r < 8; r++) {
        m_i[r] = -INFINITY;
        l_i[r] = 0.0f;
        o0[r] = 0.0f;
        o1[r] = 0.0f;
    }

    const float scale = 0.125f;  // 1/sqrt(64)
    const int tmax = 2 * rb + 1;

    for (int t = 0; t <= tmax; t++) {
        __syncthreads();
        const float* kb = g_k + ((size_t)bh * SEQ + t * 32) * DKH;
        const float* vb = g_v + ((size_t)bh * SEQ + t * 32) * DKH;
#pragma unroll
        for (int i = 0; i < 2; i++) {
            int e = tid + i * 256;
            int r = e >> 4, d4 = (e & 15) * 4;
            float4 kv = *(const float4*)(kb + r * DKH + d4);
            float4 vv = *(const float4*)(vb + r * DKH + d4);
            *(float4*)&Ks[r * QP + d4] = kv;
            *(float4*)&Vs[r * QP + d4] = vv;
        }
        __syncthreads();

        float s[8];
#pragma unroll
        for (int r = 0; r < 8; r++) s[r] = 0.0f;
#pragma unroll
        for (int d4 = 0; d4 < 16; d4++) {
            float4 kq = *(const float4*)&Ks[lane * QP + d4 * 4];
#pragma unroll
            for (int r = 0; r < 8; r++) {
                float4 qq = *(const float4*)&Qs[(warp * 8 + r) * QP + d4 * 4];
                s[r] += qq.x * kq.x + qq.y * kq.y + qq.z * kq.z + qq.w * kq.w;
            }
        }

        const bool masked = (t >= 2 * rb);
        const int col = t * 32 + lane;
#pragma unroll
        for (int r = 0; r < 8; r++) {
            const int rr = warp * 8 + r;
            const int grow = rb * 64 + rr;
            float v0 = s[r] * scale;
            if (masked && col > grow) v0 = -INFINITY;
            float mx = v0;
#pragma unroll
            for (int off = 16; off > 0; off >>= 1)
                mx = fmaxf(mx, __shfl_xor_sync(0xFFFFFFFFu, mx, off));
            const float mnew = fmaxf(m_i[r], mx);
            const float scl = __expf(m_i[r] - mnew);
            const float p0 = __expf(v0 - mnew);
            float rs = p0;
#pragma unroll
            for (int off = 16; off > 0; off >>= 1)
                rs += __shfl_xor_sync(0xFFFFFFFFu, rs, off);
            l_i[r] = l_i[r] * scl + rs;
            m_i[r] = mnew;
            o0[r] *= scl;
            o1[r] *= scl;
            Ps[rr * PP + lane] = p0;
        }
        __syncwarp();

#pragma unroll 8
        for (int c = 0; c < 32; c++) {
            float vv0 = Vs[c * QP + lane];
            float vv1 = Vs[c * QP + lane + 32];
#pragma unroll
            for (int r = 0; r < 8; r++) {
                float p = Ps[(warp * 8 + r) * PP + c];
                o0[r] += p * vv0;
                o1[r] += p * vv1;
            }
        }
        __syncwarp();
    }

    const int bb = bh >> 4, hh = bh & 15;
#pragma unroll
    for (int r = 0; r < 8; r++) {
        const int rr = warp * 8 + r;
        const int grow = rb * 64 + rr;
        const float inv = 1.0f / l_i[r];
        float* dst = g_attn + ((size_t)(bb * SEQ + grow)) * DMODEL + hh * 64;
        dst[lane] = o0[r] * inv;
        dst[lane + 32] = o1[r] * inv;
    }
}

// ============================================================
// Launch: kernel launches ONLY
// ============================================================
extern "C" void kernel_launch(void* const* d_in, const int* in_sizes, int n_in,
                              void* d_out, int out_size) {
    const float* x = (const float*)d_in[0];
    const float* wq = (const float*)d_in[1];
    const float* wk = (const float*)d_in[2];
    const float* wv = (const float*)d_in[3];
    const float* wo = (const float*)d_in[4];
    float* out = (float*)d_out;

    dim3 gemm_grid(DMODEL / 128, MTOT / 128);  // (8, 32)
    sgemm_nt<0><<<gemm_grid, 256>>>(x, wq);            // Q (fp32: precision-critical)
    sgemm_nt<1><<<gemm_grid, 256>>>(x, wk);            // K (fp32: precision-critical)
    tf32_gemm<2><<<gemm_grid, 256>>>(x, wv, nullptr);  // V (tf32 tensor core)

    dim3 attn_grid(SEQ / 64, BHTOT);  // (32, 32)
    flash_attn<<<attn_grid, 256>>>();

    tf32_gemm<3><<<gemm_grid, 256>>>(nullptr, wo, out);  // O (tf32 tensor core)
}

// round 6
// speedup vs baseline: 2.0386x; 1.6791x over previous
#include <cuda_runtime.h>
#include <math.h>
#include <stdint.h>

#define NHEADS 16
#define DKH 64
#define BATCH 2
#define SEQ 2048
#define DMODEL 1024
#define MTOT (BATCH * SEQ)      // 4096
#define BHTOT (BATCH * NHEADS)  // 32

// Scratch (__device__ globals: allocation-free)
__device__ float g_q[BHTOT * SEQ * DKH];
__device__ float g_k[BHTOT * SEQ * DKH];
__device__ float g_v[BHTOT * SEQ * DKH];
__device__ float g_attn[MTOT * DMODEL];

// ============================================================
// Common tf32 helpers (fragment layout HW-verified in R4)
// ============================================================
__device__ __forceinline__ uint32_t f2tf32(float x) {
    uint32_t r;
    asm("cvt.rna.tf32.f32 %0, %1;" : "=r"(r) : "f"(x));
    return r;
}

__device__ __forceinline__ void mma_tf32(float d[4], const uint32_t a[4],
                                         const uint32_t b[2]) {
    asm volatile(
        "mma.sync.aligned.m16n8k8.row.col.f32.tf32.tf32.f32 "
        "{%0,%1,%2,%3}, {%4,%5,%6,%7}, {%8,%9}, {%0,%1,%2,%3};\n"
        : "+f"(d[0]), "+f"(d[1]), "+f"(d[2]), "+f"(d[3])
        : "r"(a[0]), "r"(a[1]), "r"(a[2]), "r"(a[3]), "r"(b[0]), "r"(b[1]));
}

// ============================================================
// SIMT fp32 SGEMM (precision-critical Q,K projections only).
// C = A (M x K) * B (N x K)^T; DEST 0 -> g_q, 1 -> g_k (split heads)
// ============================================================
template <int DEST>
__global__ __launch_bounds__(256, 2) void sgemm_nt(const float* __restrict__ Ain,
                                                   const float* __restrict__ Bw) {
    const int K = 1024;
    __shared__ __align__(16) float As[8 * 128];
    __shared__ __align__(16) float Bs[8 * 128];

    const int tid = threadIdx.x;
    const int bm = blockIdx.y, bn = blockIdx.x;
    const int lrow = tid >> 1;
    const int kcol = (tid & 1) * 4;
    const int ty = tid >> 4;
    const int tx = tid & 15;

    const float* Aptr = Ain + (bm * 128 + lrow) * K + kcol;
    const float* Bptr = Bw + (bn * 128 + lrow) * K + kcol;

    float acc[8][8];
#pragma unroll
    for (int i = 0; i < 8; i++)
#pragma unroll
        for (int j = 0; j < 8; j++) acc[i][j] = 0.0f;

    float4 a = *(const float4*)(Aptr);
    float4 b = *(const float4*)(Bptr);

    for (int k0 = 0; k0 < K; k0 += 8) {
        As[(kcol + 0) * 128 + lrow] = a.x;
        As[(kcol + 1) * 128 + lrow] = a.y;
        As[(kcol + 2) * 128 + lrow] = a.z;
        As[(kcol + 3) * 128 + lrow] = a.w;
        Bs[(kcol + 0) * 128 + lrow] = b.x;
        Bs[(kcol + 1) * 128 + lrow] = b.y;
        Bs[(kcol + 2) * 128 + lrow] = b.z;
        Bs[(kcol + 3) * 128 + lrow] = b.w;
        __syncthreads();

        if (k0 + 8 < K) {
            a = *(const float4*)(Aptr + k0 + 8);
            b = *(const float4*)(Bptr + k0 + 8);
        }

#pragma unroll
        for (int kk = 0; kk < 8; kk++) {
            float4 a0 = *(const float4*)&As[kk * 128 + ty * 8];
            float4 a1 = *(const float4*)&As[kk * 128 + ty * 8 + 4];
            float4 b0 = *(const float4*)&Bs[kk * 128 + tx * 8];
            float4 b1 = *(const float4*)&Bs[kk * 128 + tx * 8 + 4];
            float ra[8] = {a0.x, a0.y, a0.z, a0.w, a1.x, a1.y, a1.z, a1.w};
            float rb[8] = {b0.x, b0.y, b0.z, b0.w, b1.x, b1.y, b1.z, b1.w};
#pragma unroll
            for (int i = 0; i < 8; i++)
#pragma unroll
                for (int j = 0; j < 8; j++) acc[i][j] += ra[i] * rb[j];
        }
        __syncthreads();
    }

    float* C = (DEST == 0) ? g_q : g_k;

#pragma unroll
    for (int i = 0; i < 8; i++) {
        const int m = bm * 128 + ty * 8 + i;
#pragma unroll
        for (int j = 0; j < 8; j++) {
            const int n = bn * 128 + tx * 8 + j;
            const int bb = m >> 11, ll = m & 2047;
            const int hh = n >> 6, dk = n & 63;
            C[(((bb * 16 + hh) * 2048) + ll) * 64 + dk] = acc[i][j];
        }
    }
}

// ============================================================
// TF32 tensor-core GEMM (V-proj / O-proj). Unchanged from R5.
// ============================================================
#define TP 20

template <int DEST>
__global__ __launch_bounds__(256, 2) void tf32_gemm(const float* __restrict__ Ain,
                                                    const float* __restrict__ Bw,
                                                    float* __restrict__ Cout) {
    __shared__ __align__(16) uint32_t As[128 * TP];
    __shared__ __align__(16) uint32_t Bs[128 * TP];

    const float* A = (DEST == 3) ? (const float*)g_attn : Ain;
    const int K = 1024;
    const int tid = threadIdx.x;
    const int lane = tid & 31, warp = tid >> 5;
    const int wm = warp >> 2, wn = warp & 3;
    const int g = lane >> 2, t = lane & 3;
    const int bm = blockIdx.y, bn = blockIdx.x;

    const int lm = tid >> 2;
    const int k4 = (tid & 3) * 4;

    const float* Ap = A + (size_t)(bm * 128 + lm) * K + k4;
    const float* Bp = Bw + (size_t)(bn * 128 + lm) * K + k4;

    float d[4][4][4];
#pragma unroll
    for (int i = 0; i < 4; i++)
#pragma unroll
        for (int j = 0; j < 4; j++)
#pragma unroll
            for (int c = 0; c < 4; c++) d[i][j][c] = 0.0f;

    float4 a0v = *(const float4*)(Ap);
    float4 a1v = *(const float4*)(Ap + 64 * K);
    float4 b0v = *(const float4*)(Bp);
    float4 b1v = *(const float4*)(Bp + 64 * K);

    for (int k0 = 0; k0 < K; k0 += 16) {
        uint4 s;
        s.x = f2tf32(a0v.x); s.y = f2tf32(a0v.y); s.z = f2tf32(a0v.z); s.w = f2tf32(a0v.w);
        *(uint4*)&As[lm * TP + k4] = s;
        s.x = f2tf32(a1v.x); s.y = f2tf32(a1v.y); s.z = f2tf32(a1v.z); s.w = f2tf32(a1v.w);
        *(uint4*)&As[(lm + 64) * TP + k4] = s;
        s.x = f2tf32(b0v.x); s.y = f2tf32(b0v.y); s.z = f2tf32(b0v.z); s.w = f2tf32(b0v.w);
        *(uint4*)&Bs[lm * TP + k4] = s;
        s.x = f2tf32(b1v.x); s.y = f2tf32(b1v.y); s.z = f2tf32(b1v.z); s.w = f2tf32(b1v.w);
        *(uint4*)&Bs[(lm + 64) * TP + k4] = s;
        __syncthreads();

        if (k0 + 16 < K) {
            a0v = *(const float4*)(Ap + k0 + 16);
            a1v = *(const float4*)(Ap + 64 * K + k0 + 16);
            b0v = *(const float4*)(Bp + k0 + 16);
            b1v = *(const float4*)(Bp + 64 * K + k0 + 16);
        }

#pragma unroll
        for (int ks = 0; ks < 16; ks += 8) {
            uint32_t af[4][4], bf[4][2];
#pragma unroll
            for (int mt = 0; mt < 4; mt++) {
                const int mb = wm * 64 + mt * 16 + g;
                af[mt][0] = As[mb * TP + ks + t];
                af[mt][1] = As[(mb + 8) * TP + ks + t];
                af[mt][2] = As[mb * TP + ks + t + 4];
                af[mt][3] = As[(mb + 8) * TP + ks + t + 4];
            }
#pragma unroll
            for (int nt = 0; nt < 4; nt++) {
                const int nb = wn * 32 + nt * 8 + g;
                bf[nt][0] = Bs[nb * TP + ks + t];
                bf[nt][1] = Bs[nb * TP + ks + t + 4];
            }
#pragma unroll
            for (int mt = 0; mt < 4; mt++)
#pragma unroll
                for (int nt = 0; nt < 4; nt++) mma_tf32(d[mt][nt], af[mt], bf[nt]);
        }
        __syncthreads();
    }

#pragma unroll
    for (int mt = 0; mt < 4; mt++) {
#pragma unroll
        for (int nt = 0; nt < 4; nt++) {
            const int m0 = bm * 128 + wm * 64 + mt * 16 + g;
            const int n0 = bn * 128 + wn * 32 + nt * 8 + 2 * t;
#pragma unroll
            for (int half = 0; half < 2; half++) {
                const int m = m0 + half * 8;
                const float v0 = d[mt][nt][half * 2 + 0];
                const float v1 = d[mt][nt][half * 2 + 1];
                if (DEST == 3) {
                    float2* p = (float2*)&Cout[(size_t)m * 1024 + n0];
                    *p = make_float2(v0, v1);
                } else {
                    const int bb = m >> 11, ll = m & 2047;
                    const int hh = n0 >> 6, dk = n0 & 63;
                    float2* p = (float2*)&g_v[(((size_t)(bb * 16 + hh) * 2048) + ll) * 64 + dk];
                    *p = make_float2(v0, v1);
                }
            }
        }
    }
}

// ============================================================
// Tensor-core causal flash attention (tf32 mma, fp32 softmax).
// BR=64, BC=32, dk=64. 128 threads = 4 warps; warp w owns Q rows
// [w*16, w*16+16). S and P*V via mma.m16n8k8.
// Pitches: Q/K 68 (A/B frag bank=4g+t, permutation), V 72 (8t+g,
// permutation), P 36 (4g+t, permutation). Smem 43.5KB static.
// ============================================================
#define QPT 68
#define VPT 72
#define PPT 36

__global__ __launch_bounds__(128) void flash_attn_tc() {
    __shared__ __align__(16) uint32_t Qs[64 * QPT];  // 17408 B
    __shared__ __align__(16) uint32_t Ks[32 * QPT];  //  8704 B
    __shared__ __align__(16) uint32_t Vs[32 * VPT];  //  9216 B
    __shared__ __align__(16) uint32_t Ps[64 * PPT];  //  9216 B

    const int bh = blockIdx.y;
    const int rb = blockIdx.x;
    const int tid = threadIdx.x;
    const int lane = tid & 31;
    const int warp = tid >> 5;
    const int g = lane >> 2, t = lane & 3;

    // Load Q tile (64x64) -> tf32 smem. 1024 float4 slots / 128 thr = 8 each.
    const float* qbase = g_q + ((size_t)bh * SEQ + rb * 64) * DKH;
#pragma unroll
    for (int i = 0; i < 8; i++) {
        int e = tid + i * 128;
        int r = e >> 4, d4 = (e & 15) * 4;
        float4 v = *(const float4*)(qbase + r * DKH + d4);
        uint4 u;
        u.x = f2tf32(v.x); u.y = f2tf32(v.y); u.z = f2tf32(v.z); u.w = f2tf32(v.w);
        *(uint4*)&Qs[r * QPT + d4] = u;
    }

    // Per-thread state: rows r0 = w*16+g, r1 = r0+8 (replicated over t)
    float m0 = -INFINITY, m1 = -INFINITY, l0 = 0.0f, l1 = 0.0f;
    float o[8][4];
#pragma unroll
    for (int nt = 0; nt < 8; nt++)
#pragma unroll
        for (int j = 0; j < 4; j++) o[nt][j] = 0.0f;

    const float scale = 0.125f;  // 1/sqrt(64)
    const int row0 = rb * 64 + warp * 16 + g;
    const int tmax = 2 * rb + 1;

    for (int tt = 0; tt <= tmax; tt++) {
        __syncthreads();  // prior K/V reads done
        // Load K,V tile (32x64 each) -> tf32 smem. 512 float4 each / 128 thr = 4.
        const float* kb = g_k + ((size_t)bh * SEQ + tt * 32) * DKH;
        const float* vb = g_v + ((size_t)bh * SEQ + tt * 32) * DKH;
#pragma unroll
        for (int i = 0; i < 4; i++) {
            int e = tid + i * 128;
            int r = e >> 4, d4 = (e & 15) * 4;
            float4 kv = *(const float4*)(kb + r * DKH + d4);
            float4 vv = *(const float4*)(vb + r * DKH + d4);
            uint4 u;
            u.x = f2tf32(kv.x); u.y = f2tf32(kv.y); u.z = f2tf32(kv.z); u.w = f2tf32(kv.w);
            *(uint4*)&Ks[r * QPT + d4] = u;
            u.x = f2tf32(vv.x); u.y = f2tf32(vv.y); u.z = f2tf32(vv.z); u.w = f2tf32(vv.w);
            *(uint4*)&Vs[r * VPT + d4] = u;
        }
        __syncthreads();

        // S = Q K^T : warp computes 16x32 via 4 ntiles x 8 ksteps
        float s_[4][4];
#pragma unroll
        for (int nt = 0; nt < 4; nt++)
#pragma unroll
            for (int j = 0; j < 4; j++) s_[nt][j] = 0.0f;

#pragma unroll
        for (int ks = 0; ks < 8; ks++) {
            uint32_t a[4];
            const uint32_t* qr = &Qs[(warp * 16 + g) * QPT + ks * 8];
            a[0] = qr[t];
            a[1] = qr[8 * QPT + t];
            a[2] = qr[t + 4];
            a[3] = qr[8 * QPT + t + 4];
#pragma unroll
            for (int nt = 0; nt < 4; nt++) {
                uint32_t b[2];
                const uint32_t* kr = &Ks[(nt * 8 + g) * QPT + ks * 8];
                b[0] = kr[t];
                b[1] = kr[t + 4];
                mma_tf32(s_[nt], a, b);
            }
        }

        // Softmax (fp32, online)
        const bool masked = (tt >= 2 * rb);
        const int cbase = tt * 32 + 2 * t;
        float mx0 = -INFINITY, mx1 = -INFINITY;
#pragma unroll
        for (int nt = 0; nt < 4; nt++) {
#pragma unroll
            for (int j = 0; j < 4; j++) {
                float v = s_[nt][j] * scale;
                const int col = cbase + nt * 8 + (j & 1);
                const int row = row0 + (j >> 1) * 8;
                if (masked && col > row) v = -INFINITY;
                s_[nt][j] = v;
                if (j < 2) mx0 = fmaxf(mx0, v);
                else mx1 = fmaxf(mx1, v);
            }
        }
        mx0 = fmaxf(mx0, __shfl_xor_sync(0xFFFFFFFFu, mx0, 1));
        mx0 = fmaxf(mx0, __shfl_xor_sync(0xFFFFFFFFu, mx0, 2));
        mx1 = fmaxf(mx1, __shfl_xor_sync(0xFFFFFFFFu, mx1, 1));
        mx1 = fmaxf(mx1, __shfl_xor_sync(0xFFFFFFFFu, mx1, 2));

        const float mn0 = fmaxf(m0, mx0);
        const float mn1 = fmaxf(m1, mx1);
        const float scl0 = __expf(m0 - mn0);
        const float scl1 = __expf(m1 - mn1);

        float rs0 = 0.0f, rs1 = 0.0f;
#pragma unroll
        for (int nt = 0; nt < 4; nt++) {
            float p0 = __expf(s_[nt][0] - mn0);
            float p1 = __expf(s_[nt][1] - mn0);
            float p2 = __expf(s_[nt][2] - mn1);
            float p3 = __expf(s_[nt][3] - mn1);
            rs0 += p0 + p1;
            rs1 += p2 + p3;
            // store P (tf32) to smem: rows w16+g / +8, cols nt*8+2t,+1
            uint32_t* pr = &Ps[(warp * 16 + g) * PPT + nt * 8 + 2 * t];
            *(uint2*)pr = make_uint2(f2tf32(p0), f2tf32(p1));
            *(uint2*)(pr + 8 * PPT) = make_uint2(f2tf32(p2), f2tf32(p3));
        }
        rs0 += __shfl_xor_sync(0xFFFFFFFFu, rs0, 1);
        rs0 += __shfl_xor_sync(0xFFFFFFFFu, rs0, 2);
        rs1 += __shfl_xor_sync(0xFFFFFFFFu, rs1, 1);
        rs1 += __shfl_xor_sync(0xFFFFFFFFu, rs1, 2);

        l0 = l0 * scl0 + rs0;
        l1 = l1 * scl1 + rs1;
        m0 = mn0;
        m1 = mn1;

        // rescale O accumulators
#pragma unroll
        for (int nt = 0; nt < 8; nt++) {
            o[nt][0] *= scl0;
            o[nt][1] *= scl0;
            o[nt][2] *= scl1;
            o[nt][3] *= scl1;
        }
        __syncwarp();  // P visible to warp

        // O += P V : 8 ntiles (d) x 4 ksteps (keys)
#pragma unroll
        for (int ks = 0; ks < 4; ks++) {
            uint32_t a[4];
            const uint32_t* pr = &Ps[(warp * 16 + g) * PPT + ks * 8];
            a[0] = pr[t];
            a[1] = pr[8 * PPT + t];
            a[2] = pr[t + 4];
            a[3] = pr[8 * PPT + t + 4];
#pragma unroll
            for (int nt = 0; nt < 8; nt++) {
                uint32_t b[2];
                b[0] = Vs[(ks * 8 + t) * VPT + nt * 8 + g];
                b[1] = Vs[(ks * 8 + t + 4) * VPT + nt * 8 + g];
                mma_tf32(o[nt], a, b);
            }
        }
        __syncwarp();  // P reads done before next iteration overwrites
    }

    // Write merged-head layout: (b, l, h*64+dk)
    const int bb = bh >> 4, hh = bh & 15;
    const float inv0 = 1.0f / l0;
    const float inv1 = 1.0f / l1;
    float* base0 = g_attn + ((size_t)(bb * SEQ + row0)) * DMODEL + hh * 64;
    float* base1 = base0 + (size_t)8 * DMODEL;
#pragma unroll
    for (int nt = 0; nt < 8; nt++) {
        const int c = nt * 8 + 2 * t;
        *(float2*)(base0 + c) = make_float2(o[nt][0] * inv0, o[nt][1] * inv0);
        *(float2*)(base1 + c) = make_float2(o[nt][2] * inv1, o[nt][3] * inv1);
    }
}

// ============================================================
// Launch: kernel launches ONLY
// ============================================================
extern "C" void kernel_launch(void* const* d_in, const int* in_sizes, int n_in,
                              void* d_out, int out_size) {
    const float* x = (const float*)d_in[0];
    const float* wq = (const float*)d_in[1];
    const float* wk = (const float*)d_in[2];
    const float* wv = (const float*)d_in[3];
    const float* wo = (const float*)d_in[4];
    float* out = (float*)d_out;

    dim3 gemm_grid(DMODEL / 128, MTOT / 128);  // (8, 32)
    sgemm_nt<0><<<gemm_grid, 256>>>(x, wq);            // Q (fp32 SIMT)
    sgemm_nt<1><<<gemm_grid, 256>>>(x, wk);            // K (fp32 SIMT)
    tf32_gemm<2><<<gemm_grid, 256>>>(x, wv, nullptr);  // V (tf32 TC)

    dim3 attn_grid(SEQ / 64, BHTOT);  // (32, 32)
    flash_attn_tc<<<attn_grid, 128>>>();

    tf32_gemm<3><<<gemm_grid, 256>>>(nullptr, wo, out);  // O (tf32 TC)
}

// round 7
// speedup vs baseline: 2.3418x; 1.1487x over previous
#include <cuda_runtime.h>
#include <math.h>
#include <stdint.h>

#define NHEADS 16
#define DKH 64
#define BATCH 2
#define SEQ 2048
#define DMODEL 1024
#define MTOT (BATCH * SEQ)      // 4096
#define BHTOT (BATCH * NHEADS)  // 32

// Scratch (__device__ globals: allocation-free)
__device__ float g_q[BHTOT * SEQ * DKH];
__device__ float g_k[BHTOT * SEQ * DKH];
__device__ float g_v[BHTOT * SEQ * DKH];
__device__ float g_attn[MTOT * DMODEL];

// ============================================================
// Common tf32 helpers (fragment layout HW-verified in R4/R6)
// ============================================================
__device__ __forceinline__ uint32_t f2tf32(float x) {
    uint32_t r;
    asm("cvt.rna.tf32.f32 %0, %1;" : "=r"(r) : "f"(x));
    return r;
}

__device__ __forceinline__ void mma_tf32(float d[4], const uint32_t a[4],
                                         const uint32_t b[2]) {
    asm volatile(
        "mma.sync.aligned.m16n8k8.row.col.f32.tf32.tf32.f32 "
        "{%0,%1,%2,%3}, {%4,%5,%6,%7}, {%8,%9}, {%0,%1,%2,%3};\n"
        : "+f"(d[0]), "+f"(d[1]), "+f"(d[2]), "+f"(d[3])
        : "r"(a[0]), "r"(a[1]), "r"(a[2]), "r"(a[3]), "r"(b[0]), "r"(b[1]));
}

#define TP 20

// ============================================================
// 3xTF32 tensor-core GEMM (fp32-accurate) for Q,K projections.
// x = hi + lo (tf32 each); C = lo*hi + hi*lo + hi*hi accumulated fp32.
// Same tiling as tf32_gemm: BM=BN=128, BK=16, 8 warps, 64x32 warp tile.
// DEST 0 -> g_q, DEST 1 -> g_k (split-heads epilogue).
// ============================================================
template <int DEST>
__global__ __launch_bounds__(256) void qk3_gemm(const float* __restrict__ Ain,
                                                const float* __restrict__ Bw) {
    __shared__ __align__(16) uint32_t Ah[128 * TP];
    __shared__ __align__(16) uint32_t Al[128 * TP];
    __shared__ __align__(16) uint32_t Bh[128 * TP];
    __shared__ __align__(16) uint32_t Bl[128 * TP];

    const int K = 1024;
    const int tid = threadIdx.x;
    const int lane = tid & 31, warp = tid >> 5;
    const int wm = warp >> 2, wn = warp & 3;
    const int g = lane >> 2, t = lane & 3;
    const int bm = blockIdx.y, bn = blockIdx.x;

    const int lm = tid >> 2;
    const int k4 = (tid & 3) * 4;

    const float* Ap = Ain + (size_t)(bm * 128 + lm) * K + k4;
    const float* Bp = Bw + (size_t)(bn * 128 + lm) * K + k4;

    float d[4][4][4];
#pragma unroll
    for (int i = 0; i < 4; i++)
#pragma unroll
        for (int j = 0; j < 4; j++)
#pragma unroll
            for (int c = 0; c < 4; c++) d[i][j][c] = 0.0f;

    float4 a0v = *(const float4*)(Ap);
    float4 a1v = *(const float4*)(Ap + 64 * K);
    float4 b0v = *(const float4*)(Bp);
    float4 b1v = *(const float4*)(Bp + 64 * K);

    for (int k0 = 0; k0 < K; k0 += 16) {
        uint4 h, l;
        // A rows lm, lm+64
        h.x = f2tf32(a0v.x); l.x = f2tf32(a0v.x - __uint_as_float(h.x));
        h.y = f2tf32(a0v.y); l.y = f2tf32(a0v.y - __uint_as_float(h.y));
        h.z = f2tf32(a0v.z); l.z = f2tf32(a0v.z - __uint_as_float(h.z));
        h.w = f2tf32(a0v.w); l.w = f2tf32(a0v.w - __uint_as_float(h.w));
        *(uint4*)&Ah[lm * TP + k4] = h;
        *(uint4*)&Al[lm * TP + k4] = l;
        h.x = f2tf32(a1v.x); l.x = f2tf32(a1v.x - __uint_as_float(h.x));
        h.y = f2tf32(a1v.y); l.y = f2tf32(a1v.y - __uint_as_float(h.y));
        h.z = f2tf32(a1v.z); l.z = f2tf32(a1v.z - __uint_as_float(h.z));
        h.w = f2tf32(a1v.w); l.w = f2tf32(a1v.w - __uint_as_float(h.w));
        *(uint4*)&Ah[(lm + 64) * TP + k4] = h;
        *(uint4*)&Al[(lm + 64) * TP + k4] = l;
        // B rows lm, lm+64
        h.x = f2tf32(b0v.x); l.x = f2tf32(b0v.x - __uint_as_float(h.x));
        h.y = f2tf32(b0v.y); l.y = f2tf32(b0v.y - __uint_as_float(h.y));
        h.z = f2tf32(b0v.z); l.z = f2tf32(b0v.z - __uint_as_float(h.z));
        h.w = f2tf32(b0v.w); l.w = f2tf32(b0v.w - __uint_as_float(h.w));
        *(uint4*)&Bh[lm * TP + k4] = h;
        *(uint4*)&Bl[lm * TP + k4] = l;
        h.x = f2tf32(b1v.x); l.x = f2tf32(b1v.x - __uint_as_float(h.x));
        h.y = f2tf32(b1v.y); l.y = f2tf32(b1v.y - __uint_as_float(h.y));
        h.z = f2tf32(b1v.z); l.z = f2tf32(b1v.z - __uint_as_float(h.z));
        h.w = f2tf32(b1v.w); l.w = f2tf32(b1v.w - __uint_as_float(h.w));
        *(uint4*)&Bh[(lm + 64) * TP + k4] = h;
        *(uint4*)&Bl[(lm + 64) * TP + k4] = l;
        __syncthreads();

        if (k0 + 16 < K) {
            a0v = *(const float4*)(Ap + k0 + 16);
            a1v = *(const float4*)(Ap + 64 * K + k0 + 16);
            b0v = *(const float4*)(Bp + k0 + 16);
            b1v = *(const float4*)(Bp + 64 * K + k0 + 16);
        }

#pragma unroll
        for (int ks = 0; ks < 16; ks += 8) {
            uint32_t afh[4][4], bfh[4][2];
#pragma unroll
            for (int mt = 0; mt < 4; mt++) {
                const int mb = wm * 64 + mt * 16 + g;
                afh[mt][0] = Ah[mb * TP + ks + t];
                afh[mt][1] = Ah[(mb + 8) * TP + ks + t];
                afh[mt][2] = Ah[mb * TP + ks + t + 4];
                afh[mt][3] = Ah[(mb + 8) * TP + ks + t + 4];
            }
#pragma unroll
            for (int nt = 0; nt < 4; nt++) {
                const int nb = wn * 32 + nt * 8 + g;
                bfh[nt][0] = Bh[nb * TP + ks + t];
                bfh[nt][1] = Bh[nb * TP + ks + t + 4];
            }
            // hi * hi
#pragma unroll
            for (int mt = 0; mt < 4; mt++)
#pragma unroll
                for (int nt = 0; nt < 4; nt++) mma_tf32(d[mt][nt], afh[mt], bfh[nt]);
            // lo * hi
            {
                uint32_t afl[4][4];
#pragma unroll
                for (int mt = 0; mt < 4; mt++) {
                    const int mb = wm * 64 + mt * 16 + g;
                    afl[mt][0] = Al[mb * TP + ks + t];
                    afl[mt][1] = Al[(mb + 8) * TP + ks + t];
                    afl[mt][2] = Al[mb * TP + ks + t + 4];
                    afl[mt][3] = Al[(mb + 8) * TP + ks + t + 4];
                }
#pragma unroll
                for (int mt = 0; mt < 4; mt++)
#pragma unroll
                    for (int nt = 0; nt < 4; nt++) mma_tf32(d[mt][nt], afl[mt], bfh[nt]);
            }
            // hi * lo
            {
                uint32_t bfl[4][2];
#pragma unroll
                for (int nt = 0; nt < 4; nt++) {
                    const int nb = wn * 32 + nt * 8 + g;
                    bfl[nt][0] = Bl[nb * TP + ks + t];
                    bfl[nt][1] = Bl[nb * TP + ks + t + 4];
                }
#pragma unroll
                for (int mt = 0; mt < 4; mt++)
#pragma unroll
                    for (int nt = 0; nt < 4; nt++) mma_tf32(d[mt][nt], afh[mt], bfl[nt]);
            }
        }
        __syncthreads();
    }

    float* C = (DEST == 0) ? g_q : g_k;
#pragma unroll
    for (int mt = 0; mt < 4; mt++) {
#pragma unroll
        for (int nt = 0; nt < 4; nt++) {
            const int m0 = bm * 128 + wm * 64 + mt * 16 + g;
            const int n0 = bn * 128 + wn * 32 + nt * 8 + 2 * t;
#pragma unroll
            for (int half = 0; half < 2; half++) {
                const int m = m0 + half * 8;
                // split heads: m=b*2048+l, n=h*64+dk
                const int bb = m >> 11, ll = m & 2047;
                const int hh = n0 >> 6, dk = n0 & 63;
                float2* p = (float2*)&C[(((size_t)(bb * 16 + hh) * 2048) + ll) * 64 + dk];
                *p = make_float2(d[mt][nt][half * 2 + 0], d[mt][nt][half * 2 + 1]);
            }
        }
    }
}

// ============================================================
// Plain TF32 tensor-core GEMM (V-proj / O-proj). Unchanged from R5.
// ============================================================
template <int DEST>
__global__ __launch_bounds__(256, 2) void tf32_gemm(const float* __restrict__ Ain,
                                                    const float* __restrict__ Bw,
                                                    float* __restrict__ Cout) {
    __shared__ __align__(16) uint32_t As[128 * TP];
    __shared__ __align__(16) uint32_t Bs[128 * TP];

    const float* A = (DEST == 3) ? (const float*)g_attn : Ain;
    const int K = 1024;
    const int tid = threadIdx.x;
    const int lane = tid & 31, warp = tid >> 5;
    const int wm = warp >> 2, wn = warp & 3;
    const int g = lane >> 2, t = lane & 3;
    const int bm = blockIdx.y, bn = blockIdx.x;

    const int lm = tid >> 2;
    const int k4 = (tid & 3) * 4;

    const float* Ap = A + (size_t)(bm * 128 + lm) * K + k4;
    const float* Bp = Bw + (size_t)(bn * 128 + lm) * K + k4;

    float d[4][4][4];
#pragma unroll
    for (int i = 0; i < 4; i++)
#pragma unroll
        for (int j = 0; j < 4; j++)
#pragma unroll
            for (int c = 0; c < 4; c++) d[i][j][c] = 0.0f;

    float4 a0v = *(const float4*)(Ap);
    float4 a1v = *(const float4*)(Ap + 64 * K);
    float4 b0v = *(const float4*)(Bp);
    float4 b1v = *(const float4*)(Bp + 64 * K);

    for (int k0 = 0; k0 < K; k0 += 16) {
        uint4 s;
        s.x = f2tf32(a0v.x); s.y = f2tf32(a0v.y); s.z = f2tf32(a0v.z); s.w = f2tf32(a0v.w);
        *(uint4*)&As[lm * TP + k4] = s;
        s.x = f2tf32(a1v.x); s.y = f2tf32(a1v.y); s.z = f2tf32(a1v.z); s.w = f2tf32(a1v.w);
        *(uint4*)&As[(lm + 64) * TP + k4] = s;
        s.x = f2tf32(b0v.x); s.y = f2tf32(b0v.y); s.z = f2tf32(b0v.z); s.w = f2tf32(b0v.w);
        *(uint4*)&Bs[lm * TP + k4] = s;
        s.x = f2tf32(b1v.x); s.y = f2tf32(b1v.y); s.z = f2tf32(b1v.z); s.w = f2tf32(b1v.w);
        *(uint4*)&Bs[(lm + 64) * TP + k4] = s;
        __syncthreads();

        if (k0 + 16 < K) {
            a0v = *(const float4*)(Ap + k0 + 16);
            a1v = *(const float4*)(Ap + 64 * K + k0 + 16);
            b0v = *(const float4*)(Bp + k0 + 16);
            b1v = *(const float4*)(Bp + 64 * K + k0 + 16);
        }

#pragma unroll
        for (int ks = 0; ks < 16; ks += 8) {
            uint32_t af[4][4], bf[4][2];
#pragma unroll
            for (int mt = 0; mt < 4; mt++) {
                const int mb = wm * 64 + mt * 16 + g;
                af[mt][0] = As[mb * TP + ks + t];
                af[mt][1] = As[(mb + 8) * TP + ks + t];
                af[mt][2] = As[mb * TP + ks + t + 4];
                af[mt][3] = As[(mb + 8) * TP + ks + t + 4];
            }
#pragma unroll
            for (int nt = 0; nt < 4; nt++) {
                const int nb = wn * 32 + nt * 8 + g;
                bf[nt][0] = Bs[nb * TP + ks + t];
                bf[nt][1] = Bs[nb * TP + ks + t + 4];
            }
#pragma unroll
            for (int mt = 0; mt < 4; mt++)
#pragma unroll
                for (int nt = 0; nt < 4; nt++) mma_tf32(d[mt][nt], af[mt], bf[nt]);
        }
        __syncthreads();
    }

#pragma unroll
    for (int mt = 0; mt < 4; mt++) {
#pragma unroll
        for (int nt = 0; nt < 4; nt++) {
            const int m0 = bm * 128 + wm * 64 + mt * 16 + g;
            const int n0 = bn * 128 + wn * 32 + nt * 8 + 2 * t;
#pragma unroll
            for (int half = 0; half < 2; half++) {
                const int m = m0 + half * 8;
                const float v0 = d[mt][nt][half * 2 + 0];
                const float v1 = d[mt][nt][half * 2 + 1];
                if (DEST == 3) {
                    float2* p = (float2*)&Cout[(size_t)m * 1024 + n0];
                    *p = make_float2(v0, v1);
                } else {
                    const int bb = m >> 11, ll = m & 2047;
                    const int hh = n0 >> 6, dk = n0 & 63;
                    float2* p = (float2*)&g_v[(((size_t)(bb * 16 + hh) * 2048) + ll) * 64 + dk];
                    *p = make_float2(v0, v1);
                }
            }
        }
    }
}

// ============================================================
// Tensor-core causal flash attention (tf32 mma, fp32 softmax).
// Unchanged from R6 (226us, tensor=27%).
// ============================================================
#define QPT 68
#define VPT 72
#define PPT 36

__global__ __launch_bounds__(128) void flash_attn_tc() {
    __shared__ __align__(16) uint32_t Qs[64 * QPT];
    __shared__ __align__(16) uint32_t Ks[32 * QPT];
    __shared__ __align__(16) uint32_t Vs[32 * VPT];
    __shared__ __align__(16) uint32_t Ps[64 * PPT];

    const int bh = blockIdx.y;
    const int rb = blockIdx.x;
    const int tid = threadIdx.x;
    const int lane = tid & 31;
    const int warp = tid >> 5;
    const int g = lane >> 2, t = lane & 3;

    const float* qbase = g_q + ((size_t)bh * SEQ + rb * 64) * DKH;
#pragma unroll
    for (int i = 0; i < 8; i++) {
        int e = tid + i * 128;
        int r = e >> 4, d4 = (e & 15) * 4;
        float4 v = *(const float4*)(qbase + r * DKH + d4);
        uint4 u;
        u.x = f2tf32(v.x); u.y = f2tf32(v.y); u.z = f2tf32(v.z); u.w = f2tf32(v.w);
        *(uint4*)&Qs[r * QPT + d4] = u;
    }

    float m0 = -INFINITY, m1 = -INFINITY, l0 = 0.0f, l1 = 0.0f;
    float o[8][4];
#pragma unroll
    for (int nt = 0; nt < 8; nt++)
#pragma unroll
        for (int j = 0; j < 4; j++) o[nt][j] = 0.0f;

    const float scale = 0.125f;
    const int row0 = rb * 64 + warp * 16 + g;
    const int tmax = 2 * rb + 1;

    for (int tt = 0; tt <= tmax; tt++) {
        __syncthreads();
        const float* kb = g_k + ((size_t)bh * SEQ + tt * 32) * DKH;
        const float* vb = g_v + ((size_t)bh * SEQ + tt * 32) * DKH;
#pragma unroll
        for (int i = 0; i < 4; i++) {
            int e = tid + i * 128;
            int r = e >> 4, d4 = (e & 15) * 4;
            float4 kv = *(const float4*)(kb + r * DKH + d4);
            float4 vv = *(const float4*)(vb + r * DKH + d4);
            uint4 u;
            u.x = f2tf32(kv.x); u.y = f2tf32(kv.y); u.z = f2tf32(kv.z); u.w = f2tf32(kv.w);
            *(uint4*)&Ks[r * QPT + d4] = u;
            u.x = f2tf32(vv.x); u.y = f2tf32(vv.y); u.z = f2tf32(vv.z); u.w = f2tf32(vv.w);
            *(uint4*)&Vs[r * VPT + d4] = u;
        }
        __syncthreads();

        float s_[4][4];
#pragma unroll
        for (int nt = 0; nt < 4; nt++)
#pragma unroll
            for (int j = 0; j < 4; j++) s_[nt][j] = 0.0f;

#pragma unroll
        for (int ks = 0; ks < 8; ks++) {
            uint32_t a[4];
            const uint32_t* qr = &Qs[(warp * 16 + g) * QPT + ks * 8];
            a[0] = qr[t];
            a[1] = qr[8 * QPT + t];
            a[2] = qr[t + 4];
            a[3] = qr[8 * QPT + t + 4];
#pragma unroll
            for (int nt = 0; nt < 4; nt++) {
                uint32_t b[2];
                const uint32_t* kr = &Ks[(nt * 8 + g) * QPT + ks * 8];
                b[0] = kr[t];
                b[1] = kr[t + 4];
                mma_tf32(s_[nt], a, b);
            }
        }

        const bool masked = (tt >= 2 * rb);
        const int cbase = tt * 32 + 2 * t;
        float mx0 = -INFINITY, mx1 = -INFINITY;
#pragma unroll
        for (int nt = 0; nt < 4; nt++) {
#pragma unroll
            for (int j = 0; j < 4; j++) {
                float v = s_[nt][j] * scale;
                const int col = cbase + nt * 8 + (j & 1);
                const int row = row0 + (j >> 1) * 8;
                if (masked && col > row) v = -INFINITY;
                s_[nt][j] = v;
                if (j < 2) mx0 = fmaxf(mx0, v);
                else mx1 = fmaxf(mx1, v);
            }
        }
        mx0 = fmaxf(mx0, __shfl_xor_sync(0xFFFFFFFFu, mx0, 1));
        mx0 = fmaxf(mx0, __shfl_xor_sync(0xFFFFFFFFu, mx0, 2));
        mx1 = fmaxf(mx1, __shfl_xor_sync(0xFFFFFFFFu, mx1, 1));
        mx1 = fmaxf(mx1, __shfl_xor_sync(0xFFFFFFFFu, mx1, 2));

        const float mn0 = fmaxf(m0, mx0);
        const float mn1 = fmaxf(m1, mx1);
        const float scl0 = __expf(m0 - mn0);
        const float scl1 = __expf(m1 - mn1);

        float rs0 = 0.0f, rs1 = 0.0f;
#pragma unroll
        for (int nt = 0; nt < 4; nt++) {
            float p0 = __expf(s_[nt][0] - mn0);
            float p1 = __expf(s_[nt][1] - mn0);
            float p2 = __expf(s_[nt][2] - mn1);
            float p3 = __expf(s_[nt][3] - mn1);
            rs0 += p0 + p1;
            rs1 += p2 + p3;
            uint32_t* pr = &Ps[(warp * 16 + g) * PPT + nt * 8 + 2 * t];
            *(uint2*)pr = make_uint2(f2tf32(p0), f2tf32(p1));
            *(uint2*)(pr + 8 * PPT) = make_uint2(f2tf32(p2), f2tf32(p3));
        }
        rs0 += __shfl_xor_sync(0xFFFFFFFFu, rs0, 1);
        rs0 += __shfl_xor_sync(0xFFFFFFFFu, rs0, 2);
        rs1 += __shfl_xor_sync(0xFFFFFFFFu, rs1, 1);
        rs1 += __shfl_xor_sync(0xFFFFFFFFu, rs1, 2);

        l0 = l0 * scl0 + rs0;
        l1 = l1 * scl1 + rs1;
        m0 = mn0;
        m1 = mn1;

#pragma unroll
        for (int nt = 0; nt < 8; nt++) {
            o[nt][0] *= scl0;
            o[nt][1] *= scl0;
            o[nt][2] *= scl1;
            o[nt][3] *= scl1;
        }
        __syncwarp();

#pragma unroll
        for (int ks = 0; ks < 4; ks++) {
            uint32_t a[4];
            const uint32_t* pr = &Ps[(warp * 16 + g) * PPT + ks * 8];
            a[0] = pr[t];
            a[1] = pr[8 * PPT + t];
            a[2] = pr[t + 4];
            a[3] = pr[8 * PPT + t + 4];
#pragma unroll
            for (int nt = 0; nt < 8; nt++) {
                uint32_t b[2];
                b[0] = Vs[(ks * 8 + t) * VPT + nt * 8 + g];
                b[1] = Vs[(ks * 8 + t + 4) * VPT + nt * 8 + g];
                mma_tf32(o[nt], a, b);
            }
        }
        __syncwarp();
    }

    const int bb = bh >> 4, hh = bh & 15;
    const float inv0 = 1.0f / l0;
    const float inv1 = 1.0f / l1;
    float* base0 = g_attn + ((size_t)(bb * SEQ + row0)) * DMODEL + hh * 64;
    float* base1 = base0 + (size_t)8 * DMODEL;
#pragma unroll
    for (int nt = 0; nt < 8; nt++) {
        const int c = nt * 8 + 2 * t;
        *(float2*)(base0 + c) = make_float2(o[nt][0] * inv0, o[nt][1] * inv0);
        *(float2*)(base1 + c) = make_float2(o[nt][2] * inv1, o[nt][3] * inv1);
    }
}

// ============================================================
// Launch: kernel launches ONLY
// ============================================================
extern "C" void kernel_launch(void* const* d_in, const int* in_sizes, int n_in,
                              void* d_out, int out_size) {
    const float* x = (const float*)d_in[0];
    const float* wq = (const float*)d_in[1];
    const float* wk = (const float*)d_in[2];
    const float* wv = (const float*)d_in[3];
    const float* wo = (const float*)d_in[4];
    float* out = (float*)d_out;

    dim3 gemm_grid(DMODEL / 128, MTOT / 128);  // (8, 32)
    qk3_gemm<0><<<gemm_grid, 256>>>(x, wq);            // Q (3xtf32 TC, fp32-accurate)
    qk3_gemm<1><<<gemm_grid, 256>>>(x, wk);            // K (3xtf32 TC, fp32-accurate)
    tf32_gemm<2><<<gemm_grid, 256>>>(x, wv, nullptr);  // V (tf32 TC)

    dim3 attn_grid(SEQ / 64, BHTOT);  // (32, 32)
    flash_attn_tc<<<attn_grid, 128>>>();

    tf32_gemm<3><<<gemm_grid, 256>>>(nullptr, wo, out);  // O (tf32 TC)
}

// round 8
// speedup vs baseline: 2.5622x; 1.0941x over previous
#include <cuda_runtime.h>
#include <math.h>
#include <stdint.h>

#define NHEADS 16
#define DKH 64
#define BATCH 2
#define SEQ 2048
#define DMODEL 1024
#define MTOT (BATCH * SEQ)      // 4096
#define BHTOT (BATCH * NHEADS)  // 32

// Scratch (__device__ globals: allocation-free)
__device__ float g_q[BHTOT * SEQ * DKH];
__device__ float g_k[BHTOT * SEQ * DKH];
__device__ float g_v[BHTOT * SEQ * DKH];
__device__ float g_attn[MTOT * DMODEL];

// ============================================================
// Common tf32 helpers (fragment layout HW-verified in R4/R6)
// ============================================================
__device__ __forceinline__ uint32_t f2tf32(float x) {
    uint32_t r;
    asm("cvt.rna.tf32.f32 %0, %1;" : "=r"(r) : "f"(x));
    return r;
}

__device__ __forceinline__ void mma_tf32(float d[4], const uint32_t a[4],
                                         const uint32_t b[2]) {
    asm volatile(
        "mma.sync.aligned.m16n8k8.row.col.f32.tf32.tf32.f32 "
        "{%0,%1,%2,%3}, {%4,%5,%6,%7}, {%8,%9}, {%0,%1,%2,%3};\n"
        : "+f"(d[0]), "+f"(d[1]), "+f"(d[2]), "+f"(d[3])
        : "r"(a[0]), "r"(a[1]), "r"(a[2]), "r"(a[3]), "r"(b[0]), "r"(b[1]));
}

#define TP 20

// ============================================================
// 3xTF32 tensor-core GEMM (fp32-accurate) for Q,K projections.
// NOW WITH __launch_bounds__(256, 2): cap regs at 128 to guarantee
// 2 CTAs/SM (was unbounded -> likely 1 CTA/SM, starving mma pipes).
// ============================================================
template <int DEST>
__global__ __launch_bounds__(256, 2) void qk3_gemm(const float* __restrict__ Ain,
                                                   const float* __restrict__ Bw) {
    __shared__ __align__(16) uint32_t Ah[128 * TP];
    __shared__ __align__(16) uint32_t Al[128 * TP];
    __shared__ __align__(16) uint32_t Bh[128 * TP];
    __shared__ __align__(16) uint32_t Bl[128 * TP];

    const int K = 1024;
    const int tid = threadIdx.x;
    const int lane = tid & 31, warp = tid >> 5;
    const int wm = warp >> 2, wn = warp & 3;
    const int g = lane >> 2, t = lane & 3;
    const int bm = blockIdx.y, bn = blockIdx.x;

    const int lm = tid >> 2;
    const int k4 = (tid & 3) * 4;

    const float* Ap = Ain + (size_t)(bm * 128 + lm) * K + k4;
    const float* Bp = Bw + (size_t)(bn * 128 + lm) * K + k4;

    float d[4][4][4];
#pragma unroll
    for (int i = 0; i < 4; i++)
#pragma unroll
        for (int j = 0; j < 4; j++)
#pragma unroll
            for (int c = 0; c < 4; c++) d[i][j][c] = 0.0f;

    float4 a0v = *(const float4*)(Ap);
    float4 a1v = *(const float4*)(Ap + 64 * K);
    float4 b0v = *(const float4*)(Bp);
    float4 b1v = *(const float4*)(Bp + 64 * K);

    for (int k0 = 0; k0 < K; k0 += 16) {
        uint4 h, l;
        h.x = f2tf32(a0v.x); l.x = f2tf32(a0v.x - __uint_as_float(h.x));
        h.y = f2tf32(a0v.y); l.y = f2tf32(a0v.y - __uint_as_float(h.y));
        h.z = f2tf32(a0v.z); l.z = f2tf32(a0v.z - __uint_as_float(h.z));
        h.w = f2tf32(a0v.w); l.w = f2tf32(a0v.w - __uint_as_float(h.w));
        *(uint4*)&Ah[lm * TP + k4] = h;
        *(uint4*)&Al[lm * TP + k4] = l;
        h.x = f2tf32(a1v.x); l.x = f2tf32(a1v.x - __uint_as_float(h.x));
        h.y = f2tf32(a1v.y); l.y = f2tf32(a1v.y - __uint_as_float(h.y));
        h.z = f2tf32(a1v.z); l.z = f2tf32(a1v.z - __uint_as_float(h.z));
        h.w = f2tf32(a1v.w); l.w = f2tf32(a1v.w - __uint_as_float(h.w));
        *(uint4*)&Ah[(lm + 64) * TP + k4] = h;
        *(uint4*)&Al[(lm + 64) * TP + k4] = l;
        h.x = f2tf32(b0v.x); l.x = f2tf32(b0v.x - __uint_as_float(h.x));
        h.y = f2tf32(b0v.y); l.y = f2tf32(b0v.y - __uint_as_float(h.y));
        h.z = f2tf32(b0v.z); l.z = f2tf32(b0v.z - __uint_as_float(h.z));
        h.w = f2tf32(b0v.w); l.w = f2tf32(b0v.w - __uint_as_float(h.w));
        *(uint4*)&Bh[lm * TP + k4] = h;
        *(uint4*)&Bl[lm * TP + k4] = l;
        h.x = f2tf32(b1v.x); l.x = f2tf32(b1v.x - __uint_as_float(h.x));
        h.y = f2tf32(b1v.y); l.y = f2tf32(b1v.y - __uint_as_float(h.y));
        h.z = f2tf32(b1v.z); l.z = f2tf32(b1v.z - __uint_as_float(h.z));
        h.w = f2tf32(b1v.w); l.w = f2tf32(b1v.w - __uint_as_float(h.w));
        *(uint4*)&Bh[(lm + 64) * TP + k4] = h;
        *(uint4*)&Bl[(lm + 64) * TP + k4] = l;
        __syncthreads();

        if (k0 + 16 < K) {
            a0v = *(const float4*)(Ap + k0 + 16);
            a1v = *(const float4*)(Ap + 64 * K + k0 + 16);
            b0v = *(const float4*)(Bp + k0 + 16);
            b1v = *(const float4*)(Bp + 64 * K + k0 + 16);
        }

#pragma unroll
        for (int ks = 0; ks < 16; ks += 8) {
            uint32_t afh[4][4], bfh[4][2];
#pragma unroll
            for (int mt = 0; mt < 4; mt++) {
                const int mb = wm * 64 + mt * 16 + g;
                afh[mt][0] = Ah[mb * TP + ks + t];
                afh[mt][1] = Ah[(mb + 8) * TP + ks + t];
                afh[mt][2] = Ah[mb * TP + ks + t + 4];
                afh[mt][3] = Ah[(mb + 8) * TP + ks + t + 4];
            }
#pragma unroll
            for (int nt = 0; nt < 4; nt++) {
                const int nb = wn * 32 + nt * 8 + g;
                bfh[nt][0] = Bh[nb * TP + ks + t];
                bfh[nt][1] = Bh[nb * TP + ks + t + 4];
            }
            // hi * hi
#pragma unroll
            for (int mt = 0; mt < 4; mt++)
#pragma unroll
                for (int nt = 0; nt < 4; nt++) mma_tf32(d[mt][nt], afh[mt], bfh[nt]);
            // lo * hi
            {
                uint32_t afl[4][4];
#pragma unroll
                for (int mt = 0; mt < 4; mt++) {
                    const int mb = wm * 64 + mt * 16 + g;
                    afl[mt][0] = Al[mb * TP + ks + t];
                    afl[mt][1] = Al[(mb + 8) * TP + ks + t];
                    afl[mt][2] = Al[mb * TP + ks + t + 4];
                    afl[mt][3] = Al[(mb + 8) * TP + ks + t + 4];
                }
#pragma unroll
                for (int mt = 0; mt < 4; mt++)
#pragma unroll
                    for (int nt = 0; nt < 4; nt++) mma_tf32(d[mt][nt], afl[mt], bfh[nt]);
            }
            // hi * lo
            {
                uint32_t bfl[4][2];
#pragma unroll
                for (int nt = 0; nt < 4; nt++) {
                    const int nb = wn * 32 + nt * 8 + g;
                    bfl[nt][0] = Bl[nb * TP + ks + t];
                    bfl[nt][1] = Bl[nb * TP + ks + t + 4];
                }
#pragma unroll
                for (int mt = 0; mt < 4; mt++)
#pragma unroll
                    for (int nt = 0; nt < 4; nt++) mma_tf32(d[mt][nt], afh[mt], bfl[nt]);
            }
        }
        __syncthreads();
    }

    float* C = (DEST == 0) ? g_q : g_k;
#pragma unroll
    for (int mt = 0; mt < 4; mt++) {
#pragma unroll
        for (int nt = 0; nt < 4; nt++) {
            const int m0 = bm * 128 + wm * 64 + mt * 16 + g;
            const int n0 = bn * 128 + wn * 32 + nt * 8 + 2 * t;
#pragma unroll
            for (int half = 0; half < 2; half++) {
                const int m = m0 + half * 8;
                const int bb = m >> 11, ll = m & 2047;
                const int hh = n0 >> 6, dk = n0 & 63;
                float2* p = (float2*)&C[(((size_t)(bb * 16 + hh) * 2048) + ll) * 64 + dk];
                *p = make_float2(d[mt][nt][half * 2 + 0], d[mt][nt][half * 2 + 1]);
            }
        }
    }
}

// ============================================================
// Plain TF32 tensor-core GEMM (V-proj / O-proj). Unchanged.
// ============================================================
template <int DEST>
__global__ __launch_bounds__(256, 2) void tf32_gemm(const float* __restrict__ Ain,
                                                    const float* __restrict__ Bw,
                                                    float* __restrict__ Cout) {
    __shared__ __align__(16) uint32_t As[128 * TP];
    __shared__ __align__(16) uint32_t Bs[128 * TP];

    const float* A = (DEST == 3) ? (const float*)g_attn : Ain;
    const int K = 1024;
    const int tid = threadIdx.x;
    const int lane = tid & 31, warp = tid >> 5;
    const int wm = warp >> 2, wn = warp & 3;
    const int g = lane >> 2, t = lane & 3;
    const int bm = blockIdx.y, bn = blockIdx.x;

    const int lm = tid >> 2;
    const int k4 = (tid & 3) * 4;

    const float* Ap = A + (size_t)(bm * 128 + lm) * K + k4;
    const float* Bp = Bw + (size_t)(bn * 128 + lm) * K + k4;

    float d[4][4][4];
#pragma unroll
    for (int i = 0; i < 4; i++)
#pragma unroll
        for (int j = 0; j < 4; j++)
#pragma unroll
            for (int c = 0; c < 4; c++) d[i][j][c] = 0.0f;

    float4 a0v = *(const float4*)(Ap);
    float4 a1v = *(const float4*)(Ap + 64 * K);
    float4 b0v = *(const float4*)(Bp);
    float4 b1v = *(const float4*)(Bp + 64 * K);

    for (int k0 = 0; k0 < K; k0 += 16) {
        uint4 s;
        s.x = f2tf32(a0v.x); s.y = f2tf32(a0v.y); s.z = f2tf32(a0v.z); s.w = f2tf32(a0v.w);
        *(uint4*)&As[lm * TP + k4] = s;
        s.x = f2tf32(a1v.x); s.y = f2tf32(a1v.y); s.z = f2tf32(a1v.z); s.w = f2tf32(a1v.w);
        *(uint4*)&As[(lm + 64) * TP + k4] = s;
        s.x = f2tf32(b0v.x); s.y = f2tf32(b0v.y); s.z = f2tf32(b0v.z); s.w = f2tf32(b0v.w);
        *(uint4*)&Bs[lm * TP + k4] = s;
        s.x = f2tf32(b1v.x); s.y = f2tf32(b1v.y); s.z = f2tf32(b1v.z); s.w = f2tf32(b1v.w);
        *(uint4*)&Bs[(lm + 64) * TP + k4] = s;
        __syncthreads();

        if (k0 + 16 < K) {
            a0v = *(const float4*)(Ap + k0 + 16);
            a1v = *(const float4*)(Ap + 64 * K + k0 + 16);
            b0v = *(const float4*)(Bp + k0 + 16);
            b1v = *(const float4*)(Bp + 64 * K + k0 + 16);
        }

#pragma unroll
        for (int ks = 0; ks < 16; ks += 8) {
            uint32_t af[4][4], bf[4][2];
#pragma unroll
            for (int mt = 0; mt < 4; mt++) {
                const int mb = wm * 64 + mt * 16 + g;
                af[mt][0] = As[mb * TP + ks + t];
                af[mt][1] = As[(mb + 8) * TP + ks + t];
                af[mt][2] = As[mb * TP + ks + t + 4];
                af[mt][3] = As[(mb + 8) * TP + ks + t + 4];
            }
#pragma unroll
            for (int nt = 0; nt < 4; nt++) {
                const int nb = wn * 32 + nt * 8 + g;
                bf[nt][0] = Bs[nb * TP + ks + t];
                bf[nt][1] = Bs[nb * TP + ks + t + 4];
            }
#pragma unroll
            for (int mt = 0; mt < 4; mt++)
#pragma unroll
                for (int nt = 0; nt < 4; nt++) mma_tf32(d[mt][nt], af[mt], bf[nt]);
        }
        __syncthreads();
    }

#pragma unroll
    for (int mt = 0; mt < 4; mt++) {
#pragma unroll
        for (int nt = 0; nt < 4; nt++) {
            const int m0 = bm * 128 + wm * 64 + mt * 16 + g;
            const int n0 = bn * 128 + wn * 32 + nt * 8 + 2 * t;
#pragma unroll
            for (int half = 0; half < 2; half++) {
                const int m = m0 + half * 8;
                const float v0 = d[mt][nt][half * 2 + 0];
                const float v1 = d[mt][nt][half * 2 + 1];
                if (DEST == 3) {
                    float2* p = (float2*)&Cout[(size_t)m * 1024 + n0];
                    *p = make_float2(v0, v1);
                } else {
                    const int bb = m >> 11, ll = m & 2047;
                    const int hh = n0 >> 6, dk = n0 & 63;
                    float2* p = (float2*)&g_v[(((size_t)(bb * 16 + hh) * 2048) + ll) * 64 + dk];
                    *p = make_float2(v0, v1);
                }
            }
        }
    }
}

// ============================================================
// Tensor-core causal flash attention (tf32 mma, fp32 softmax).
// R8: Q fragments loaded ONCE from gmem into registers (loop-
// invariant) — removes the Qs smem array (45->27KB) and all
// per-tile Q fragment LDS (~20% of smem wavefronts).
// __launch_bounds__(128,4): 4 CTAs/SM.
// ============================================================
#define QPT 68
#define VPT 72
#define PPT 36

__global__ __launch_bounds__(128, 4) void flash_attn_tc() {
    __shared__ __align__(16) uint32_t Ks[32 * QPT];  // 8704 B
    __shared__ __align__(16) uint32_t Vs[32 * VPT];  // 9216 B
    __shared__ __align__(16) uint32_t Ps[64 * PPT];  // 9216 B

    const int bh = blockIdx.y;
    const int rb = blockIdx.x;
    const int tid = threadIdx.x;
    const int lane = tid & 31;
    const int warp = tid >> 5;
    const int g = lane >> 2, t = lane & 3;

    // Q fragments: loaded once, straight from gmem (read-once data).
    const float* qbase = g_q + ((size_t)bh * SEQ + rb * 64) * DKH;
    const int r0 = warp * 16 + g, r1 = r0 + 8;
    uint32_t qa[8][4];
#pragma unroll
    for (int ks = 0; ks < 8; ks++) {
        qa[ks][0] = f2tf32(qbase[r0 * DKH + ks * 8 + t]);
        qa[ks][1] = f2tf32(qbase[r1 * DKH + ks * 8 + t]);
        qa[ks][2] = f2tf32(qbase[r0 * DKH + ks * 8 + t + 4]);
        qa[ks][3] = f2tf32(qbase[r1 * DKH + ks * 8 + t + 4]);
    }

    float m0 = -INFINITY, m1 = -INFINITY, l0 = 0.0f, l1 = 0.0f;
    float o[8][4];
#pragma unroll
    for (int nt = 0; nt < 8; nt++)
#pragma unroll
        for (int j = 0; j < 4; j++) o[nt][j] = 0.0f;

    const float scale = 0.125f;
    const int row0 = rb * 64 + warp * 16 + g;
    const int tmax = 2 * rb + 1;

    for (int tt = 0; tt <= tmax; tt++) {
        __syncthreads();
        const float* kb = g_k + ((size_t)bh * SEQ + tt * 32) * DKH;
        const float* vb = g_v + ((size_t)bh * SEQ + tt * 32) * DKH;
#pragma unroll
        for (int i = 0; i < 4; i++) {
            int e = tid + i * 128;
            int r = e >> 4, d4 = (e & 15) * 4;
            float4 kv = *(const float4*)(kb + r * DKH + d4);
            float4 vv = *(const float4*)(vb + r * DKH + d4);
            uint4 u;
            u.x = f2tf32(kv.x); u.y = f2tf32(kv.y); u.z = f2tf32(kv.z); u.w = f2tf32(kv.w);
            *(uint4*)&Ks[r * QPT + d4] = u;
            u.x = f2tf32(vv.x); u.y = f2tf32(vv.y); u.z = f2tf32(vv.z); u.w = f2tf32(vv.w);
            *(uint4*)&Vs[r * VPT + d4] = u;
        }
        __syncthreads();

        float s_[4][4];
#pragma unroll
        for (int nt = 0; nt < 4; nt++)
#pragma unroll
            for (int j = 0; j < 4; j++) s_[nt][j] = 0.0f;

#pragma unroll
        for (int ks = 0; ks < 8; ks++) {
#pragma unroll
            for (int nt = 0; nt < 4; nt++) {
                uint32_t b[2];
                const uint32_t* kr = &Ks[(nt * 8 + g) * QPT + ks * 8];
                b[0] = kr[t];
                b[1] = kr[t + 4];
                mma_tf32(s_[nt], qa[ks], b);
            }
        }

        const bool masked = (tt >= 2 * rb);
        const int cbase = tt * 32 + 2 * t;
        float mx0 = -INFINITY, mx1 = -INFINITY;
#pragma unroll
        for (int nt = 0; nt < 4; nt++) {
#pragma unroll
            for (int j = 0; j < 4; j++) {
                float v = s_[nt][j] * scale;
                const int col = cbase + nt * 8 + (j & 1);
                const int row = row0 + (j >> 1) * 8;
                if (masked && col > row) v = -INFINITY;
                s_[nt][j] = v;
                if (j < 2) mx0 = fmaxf(mx0, v);
                else mx1 = fmaxf(mx1, v);
            }
        }
        mx0 = fmaxf(mx0, __shfl_xor_sync(0xFFFFFFFFu, mx0, 1));
        mx0 = fmaxf(mx0, __shfl_xor_sync(0xFFFFFFFFu, mx0, 2));
        mx1 = fmaxf(mx1, __shfl_xor_sync(0xFFFFFFFFu, mx1, 1));
        mx1 = fmaxf(mx1, __shfl_xor_sync(0xFFFFFFFFu, mx1, 2));

        const float mn0 = fmaxf(m0, mx0);
        const float mn1 = fmaxf(m1, mx1);
        const float scl0 = __expf(m0 - mn0);
        const float scl1 = __expf(m1 - mn1);

        float rs0 = 0.0f, rs1 = 0.0f;
#pragma unroll
        for (int nt = 0; nt < 4; nt++) {
            float p0 = __expf(s_[nt][0] - mn0);
            float p1 = __expf(s_[nt][1] - mn0);
            float p2 = __expf(s_[nt][2] - mn1);
            float p3 = __expf(s_[nt][3] - mn1);
            rs0 += p0 + p1;
            rs1 += p2 + p3;
            uint32_t* pr = &Ps[(warp * 16 + g) * PPT + nt * 8 + 2 * t];
            *(uint2*)pr = make_uint2(f2tf32(p0), f2tf32(p1));
            *(uint2*)(pr + 8 * PPT) = make_uint2(f2tf32(p2), f2tf32(p3));
        }
        rs0 += __shfl_xor_sync(0xFFFFFFFFu, rs0, 1);
        rs0 += __shfl_xor_sync(0xFFFFFFFFu, rs0, 2);
        rs1 += __shfl_xor_sync(0xFFFFFFFFu, rs1, 1);
        rs1 += __shfl_xor_sync(0xFFFFFFFFu, rs1, 2);

        l0 = l0 * scl0 + rs0;
        l1 = l1 * scl1 + rs1;
        m0 = mn0;
        m1 = mn1;

#pragma unroll
        for (int nt = 0; nt < 8; nt++) {
            o[nt][0] *= scl0;
            o[nt][1] *= scl0;
            o[nt][2] *= scl1;
            o[nt][3] *= scl1;
        }
        __syncwarp();

#pragma unroll
        for (int ks = 0; ks < 4; ks++) {
            uint32_t a[4];
            const uint32_t* pr = &Ps[(warp * 16 + g) * PPT + ks * 8];
            a[0] = pr[t];
            a[1] = pr[8 * PPT + t];
            a[2] = pr[t + 4];
            a[3] = pr[8 * PPT + t + 4];
#pragma unroll
            for (int nt = 0; nt < 8; nt++) {
                uint32_t b[2];
                b[0] = Vs[(ks * 8 + t) * VPT + nt * 8 + g];
                b[1] = Vs[(ks * 8 + t + 4) * VPT + nt * 8 + g];
                mma_tf32(o[nt], a, b);
            }
        }
        __syncwarp();
    }

    const int bb = bh >> 4, hh = bh & 15;
    const float inv0 = 1.0f / l0;
    const float inv1 = 1.0f / l1;
    float* base0 = g_attn + ((size_t)(bb * SEQ + row0)) * DMODEL + hh * 64;
    float* base1 = base0 + (size_t)8 * DMODEL;
#pragma unroll
    for (int nt = 0; nt < 8; nt++) {
        const int c = nt * 8 + 2 * t;
        *(float2*)(base0 + c) = make_float2(o[nt][0] * inv0, o[nt][1] * inv0);
        *(float2*)(base1 + c) = make_float2(o[nt][2] * inv1, o[nt][3] * inv1);
    }
}

// ============================================================
// Launch: kernel launches ONLY
// ============================================================
extern "C" void kernel_launch(void* const* d_in, const int* in_sizes, int n_in,
                              void* d_out, int out_size) {
    const float* x = (const float*)d_in[0];
    const float* wq = (const float*)d_in[1];
    const float* wk = (const float*)d_in[2];
    const float* wv = (const float*)d_in[3];
    const float* wo = (const float*)d_in[4];
    float* out = (float*)d_out;

    dim3 gemm_grid(DMODEL / 128, MTOT / 128);  // (8, 32)
    qk3_gemm<0><<<gemm_grid, 256>>>(x, wq);            // Q (3xtf32 TC)
    qk3_gemm<1><<<gemm_grid, 256>>>(x, wk);            // K (3xtf32 TC)
    tf32_gemm<2><<<gemm_grid, 256>>>(x, wv, nullptr);  // V (tf32 TC)

    dim3 attn_grid(SEQ / 64, BHTOT);  // (32, 32)
    flash_attn_tc<<<attn_grid, 128>>>();

    tf32_gemm<3><<<gemm_grid, 256>>>(nullptr, wo, out);  // O (tf32 TC)
}

// round 11
// speedup vs baseline: 3.1866x; 1.2437x over previous
#include <cuda_runtime.h>
#include <cuda_bf16.h>
#include <math.h>
#include <stdint.h>

#define NHEADS 16
#define DKH 64
#define BATCH 2
#define SEQ 2048
#define DMODEL 1024
#define MTOT (BATCH * SEQ)      // 4096
#define BHTOT (BATCH * NHEADS)  // 32

// Scratch (__device__ globals: allocation-free)
__device__ float g_q[BHTOT * SEQ * DKH];
__device__ float g_k[BHTOT * SEQ * DKH];
__device__ float g_v[BHTOT * SEQ * DKH];
__device__ float g_attn[MTOT * DMODEL];

// ============================================================
// mma helpers (tf32 layout HW-verified R4/R6; bf16 same C layout)
// ============================================================
__device__ __forceinline__ uint32_t f2tf32(float x) {
    uint32_t r;
    asm("cvt.rna.tf32.f32 %0, %1;" : "=r"(r) : "f"(x));
    return r;
}

__device__ __forceinline__ void mma_tf32(float d[4], const uint32_t a[4],
                                         const uint32_t b[2]) {
    asm volatile(
        "mma.sync.aligned.m16n8k8.row.col.f32.tf32.tf32.f32 "
        "{%0,%1,%2,%3}, {%4,%5,%6,%7}, {%8,%9}, {%0,%1,%2,%3};\n"
        : "+f"(d[0]), "+f"(d[1]), "+f"(d[2]), "+f"(d[3])
        : "r"(a[0]), "r"(a[1]), "r"(a[2]), "r"(a[3]), "r"(b[0]), "r"(b[1]));
}

__device__ __forceinline__ void mma_bf16(float d[4], const uint32_t a[4],
                                         const uint32_t b[2]) {
    asm volatile(
        "mma.sync.aligned.m16n8k16.row.col.f32.bf16.bf16.f32 "
        "{%0,%1,%2,%3}, {%4,%5,%6,%7}, {%8,%9}, {%0,%1,%2,%3};\n"
        : "+f"(d[0]), "+f"(d[1]), "+f"(d[2]), "+f"(d[3])
        : "r"(a[0]), "r"(a[1]), "r"(a[2]), "r"(a[3]), "r"(b[0]), "r"(b[1]));
}

// Split float4 into bf16 hi-pairs and lo-pairs (element 2j in low 16 bits).
__device__ __forceinline__ void cvt_hilo(float4 v, uint2& h, uint2& l) {
    __nv_bfloat16 h0 = __float2bfloat16_rn(v.x);
    __nv_bfloat16 h1 = __float2bfloat16_rn(v.y);
    __nv_bfloat16 h2 = __float2bfloat16_rn(v.z);
    __nv_bfloat16 h3 = __float2bfloat16_rn(v.w);
    __nv_bfloat16 l0 = __float2bfloat16_rn(v.x - __bfloat162float(h0));
    __nv_bfloat16 l1 = __float2bfloat16_rn(v.y - __bfloat162float(h1));
    __nv_bfloat16 l2 = __float2bfloat16_rn(v.z - __bfloat162float(h2));
    __nv_bfloat16 l3 = __float2bfloat16_rn(v.w - __bfloat162float(h3));
    __nv_bfloat162 hp0 = __halves2bfloat162(h0, h1);
    __nv_bfloat162 hp1 = __halves2bfloat162(h2, h3);
    __nv_bfloat162 lp0 = __halves2bfloat162(l0, l1);
    __nv_bfloat162 lp1 = __halves2bfloat162(l2, l3);
    h.x = *(uint32_t*)&hp0;
    h.y = *(uint32_t*)&hp1;
    l.x = *(uint32_t*)&lp0;
    l.y = *(uint32_t*)&lp1;
}

// ============================================================
// BF16x3 tensor-core GEMM (fp32-accurate) for Q,K projections.
// x = hi + lo (bf16 each); C = hi*hi + lo*hi + hi*lo, fp32 accum.
// mma.m16n8k16.bf16: one k16 step per BK=16, 48 mmas/iter (was 96
// k8 tf32 mmas) and half the fragment LDS. Row pitch 12 words
// (8 data + 4 pad): frag bank (12g+t)%32 is a full permutation.
// DEST 0 -> g_q, DEST 1 -> g_k (split-heads epilogue).
// ============================================================
#define BP 12

template <int DEST>
__global__ __launch_bounds__(256, 2) void qk3_gemm(const float* __restrict__ Ain,
                                                   const float* __restrict__ Bw) {
    __shared__ __align__(16) uint32_t Ah[128 * BP];
    __shared__ __align__(16) uint32_t Al[128 * BP];
    __shared__ __align__(16) uint32_t Bh[128 * BP];
    __shared__ __align__(16) uint32_t Bl[128 * BP];

    const int K = 1024;
    const int tid = threadIdx.x;
    const int lane = tid & 31, warp = tid >> 5;
    const int wm = warp >> 2, wn = warp & 3;
    const int g = lane >> 2, t = lane & 3;
    const int bm = blockIdx.y, bn = blockIdx.x;

    const int lm = tid >> 2;          // 0..63 (row; also +64)
    const int kw = (tid & 3) * 2;     // word offset 0,2,4,6 (bf16 pairs)
    const int k4 = (tid & 3) * 4;     // float offset

    const float* Ap = Ain + (size_t)(bm * 128 + lm) * K + k4;
    const float* Bp = Bw + (size_t)(bn * 128 + lm) * K + k4;

    float d[4][4][4];
#pragma unroll
    for (int i = 0; i < 4; i++)
#pragma unroll
        for (int j = 0; j < 4; j++)
#pragma unroll
            for (int c = 0; c < 4; c++) d[i][j][c] = 0.0f;

    float4 a0v = *(const float4*)(Ap);
    float4 a1v = *(const float4*)(Ap + 64 * K);
    float4 b0v = *(const float4*)(Bp);
    float4 b1v = *(const float4*)(Bp + 64 * K);

    for (int k0 = 0; k0 < K; k0 += 16) {
        uint2 h, l;
        cvt_hilo(a0v, h, l);
        *(uint2*)&Ah[lm * BP + kw] = h;
        *(uint2*)&Al[lm * BP + kw] = l;
        cvt_hilo(a1v, h, l);
        *(uint2*)&Ah[(lm + 64) * BP + kw] = h;
        *(uint2*)&Al[(lm + 64) * BP + kw] = l;
        cvt_hilo(b0v, h, l);
        *(uint2*)&Bh[lm * BP + kw] = h;
        *(uint2*)&Bl[lm * BP + kw] = l;
        cvt_hilo(b1v, h, l);
        *(uint2*)&Bh[(lm + 64) * BP + kw] = h;
        *(uint2*)&Bl[(lm + 64) * BP + kw] = l;
        __syncthreads();

        if (k0 + 16 < K) {
            a0v = *(const float4*)(Ap + k0 + 16);
            a1v = *(const float4*)(Ap + 64 * K + k0 + 16);
            b0v = *(const float4*)(Bp + k0 + 16);
            b1v = *(const float4*)(Bp + 64 * K + k0 + 16);
        }

        uint32_t afh[4][4], bfh[4][2];
#pragma unroll
        for (int mt = 0; mt < 4; mt++) {
            const int mb = wm * 64 + mt * 16 + g;
            afh[mt][0] = Ah[mb * BP + t];
            afh[mt][1] = Ah[(mb + 8) * BP + t];
            afh[mt][2] = Ah[mb * BP + t + 4];
            afh[mt][3] = Ah[(mb + 8) * BP + t + 4];
        }
#pragma unroll
        for (int nt = 0; nt < 4; nt++) {
            const int nb = wn * 32 + nt * 8 + g;
            bfh[nt][0] = Bh[nb * BP + t];
            bfh[nt][1] = Bh[nb * BP + t + 4];
        }
        // hi * hi
#pragma unroll
        for (int mt = 0; mt < 4; mt++)
#pragma unroll
            for (int nt = 0; nt < 4; nt++) mma_bf16(d[mt][nt], afh[mt], bfh[nt]);
        // lo * hi
        {
            uint32_t afl[4][4];
#pragma unroll
            for (int mt = 0; mt < 4; mt++) {
                const int mb = wm * 64 + mt * 16 + g;
                afl[mt][0] = Al[mb * BP + t];
                afl[mt][1] = Al[(mb + 8) * BP + t];
                afl[mt][2] = Al[mb * BP + t + 4];
                afl[mt][3] = Al[(mb + 8) * BP + t + 4];
            }
#pragma unroll
            for (int mt = 0; mt < 4; mt++)
#pragma unroll
                for (int nt = 0; nt < 4; nt++) mma_bf16(d[mt][nt], afl[mt], bfh[nt]);
        }
        // hi * lo
        {
            uint32_t bfl[4][2];
#pragma unroll
            for (int nt = 0; nt < 4; nt++) {
                const int nb = wn * 32 + nt * 8 + g;
                bfl[nt][0] = Bl[nb * BP + t];
                bfl[nt][1] = Bl[nb * BP + t + 4];
            }
#pragma unroll
            for (int mt = 0; mt < 4; mt++)
#pragma unroll
                for (int nt = 0; nt < 4; nt++) mma_bf16(d[mt][nt], afh[mt], bfl[nt]);
        }
        __syncthreads();
    }

    float* C = (DEST == 0) ? g_q : g_k;
#pragma unroll
    for (int mt = 0; mt < 4; mt++) {
#pragma unroll
        for (int nt = 0; nt < 4; nt++) {
            const int m0 = bm * 128 + wm * 64 + mt * 16 + g;
            const int n0 = bn * 128 + wn * 32 + nt * 8 + 2 * t;
#pragma unroll
            for (int half = 0; half < 2; half++) {
                const int m = m0 + half * 8;
                const int bb = m >> 11, ll = m & 2047;
                const int hh = n0 >> 6, dk = n0 & 63;
                float2* p = (float2*)&C[(((size_t)(bb * 16 + hh) * 2048) + ll) * 64 + dk];
                *p = make_float2(d[mt][nt][half * 2 + 0], d[mt][nt][half * 2 + 1]);
            }
        }
    }
}

// ============================================================
// Plain TF32 tensor-core GEMM (V-proj / O-proj). Unchanged.
// ============================================================
#define TP 20

template <int DEST>
__global__ __launch_bounds__(256, 2) void tf32_gemm(const float* __restrict__ Ain,
                                                    const float* __restrict__ Bw,
                                                    float* __restrict__ Cout) {
    __shared__ __align__(16) uint32_t As[128 * TP];
    __shared__ __align__(16) uint32_t Bs[128 * TP];

    const float* A = (DEST == 3) ? (const float*)g_attn : Ain;
    const int K = 1024;
    const int tid = threadIdx.x;
    const int lane = tid & 31, warp = tid >> 5;
    const int wm = warp >> 2, wn = warp & 3;
    const int g = lane >> 2, t = lane & 3;
    const int bm = blockIdx.y, bn = blockIdx.x;

    const int lm = tid >> 2;
    const int k4 = (tid & 3) * 4;

    const float* Ap = A + (size_t)(bm * 128 + lm) * K + k4;
    const float* Bp = Bw + (size_t)(bn * 128 + lm) * K + k4;

    float d[4][4][4];
#pragma unroll
    for (int i = 0; i < 4; i++)
#pragma unroll
        for (int j = 0; j < 4; j++)
#pragma unroll
            for (int c = 0; c < 4; c++) d[i][j][c] = 0.0f;

    float4 a0v = *(const float4*)(Ap);
    float4 a1v = *(const float4*)(Ap + 64 * K);
    float4 b0v = *(const float4*)(Bp);
    float4 b1v = *(const float4*)(Bp + 64 * K);

    for (int k0 = 0; k0 < K; k0 += 16) {
        uint4 s;
        s.x = f2tf32(a0v.x); s.y = f2tf32(a0v.y); s.z = f2tf32(a0v.z); s.w = f2tf32(a0v.w);
        *(uint4*)&As[lm * TP + k4] = s;
        s.x = f2tf32(a1v.x); s.y = f2tf32(a1v.y); s.z = f2tf32(a1v.z); s.w = f2tf32(a1v.w);
        *(uint4*)&As[(lm + 64) * TP + k4] = s;
        s.x = f2tf32(b0v.x); s.y = f2tf32(b0v.y); s.z = f2tf32(b0v.z); s.w = f2tf32(b0v.w);
        *(uint4*)&Bs[lm * TP + k4] = s;
        s.x = f2tf32(b1v.x); s.y = f2tf32(b1v.y); s.z = f2tf32(b1v.z); s.w = f2tf32(b1v.w);
        *(uint4*)&Bs[(lm + 64) * TP + k4] = s;
        __syncthreads();

        if (k0 + 16 < K) {
            a0v = *(const float4*)(Ap + k0 + 16);
            a1v = *(const float4*)(Ap + 64 * K + k0 + 16);
            b0v = *(const float4*)(Bp + k0 + 16);
            b1v = *(const float4*)(Bp + 64 * K + k0 + 16);
        }

#pragma unroll
        for (int ks = 0; ks < 16; ks += 8) {
            uint32_t af[4][4], bf[4][2];
#pragma unroll
            for (int mt = 0; mt < 4; mt++) {
                const int mb = wm * 64 + mt * 16 + g;
                af[mt][0] = As[mb * TP + ks + t];
                af[mt][1] = As[(mb + 8) * TP + ks + t];
                af[mt][2] = As[mb * TP + ks + t + 4];
                af[mt][3] = As[(mb + 8) * TP + ks + t + 4];
            }
#pragma unroll
            for (int nt = 0; nt < 4; nt++) {
                const int nb = wn * 32 + nt * 8 + g;
                bf[nt][0] = Bs[nb * TP + ks + t];
                bf[nt][1] = Bs[nb * TP + ks + t + 4];
            }
#pragma unroll
            for (int mt = 0; mt < 4; mt++)
#pragma unroll
                for (int nt = 0; nt < 4; nt++) mma_tf32(d[mt][nt], af[mt], bf[nt]);
        }
        __syncthreads();
    }

#pragma unroll
    for (int mt = 0; mt < 4; mt++) {
#pragma unroll
        for (int nt = 0; nt < 4; nt++) {
            const int m0 = bm * 128 + wm * 64 + mt * 16 + g;
            const int n0 = bn * 128 + wn * 32 + nt * 8 + 2 * t;
#pragma unroll
            for (int half = 0; half < 2; half++) {
                const int m = m0 + half * 8;
                const float v0 = d[mt][nt][half * 2 + 0];
                const float v1 = d[mt][nt][half * 2 + 1];
                if (DEST == 3) {
                    float2* p = (float2*)&Cout[(size_t)m * 1024 + n0];
                    *p = make_float2(v0, v1);
                } else {
                    const int bb = m >> 11, ll = m & 2047;
                    const int hh = n0 >> 6, dk = n0 & 63;
                    float2* p = (float2*)&g_v[(((size_t)(bb * 16 + hh) * 2048) + ll) * 64 + dk];
                    *p = make_float2(v0, v1);
                }
            }
        }
    }
}

// ============================================================
// Tensor-core causal flash attention (tf32 mma, fp32 softmax).
// R9: double-buffered K/V smem + register prefetch of next tile.
// ONE __syncthreads per tile; gmem latency hidden under mmas.
// Smem 45KB; __launch_bounds__(128,3) absorbs prefetch regs.
// ============================================================
#define QPT 68
#define VPT 72
#define PPT 36

__global__ __launch_bounds__(128, 3) void flash_attn_tc() {
    __shared__ __align__(16) uint32_t Ks[2][32 * QPT];  // 2 x 8704 B
    __shared__ __align__(16) uint32_t Vs[2][32 * VPT];  // 2 x 9216 B
    __shared__ __align__(16) uint32_t Ps[64 * PPT];     //     9216 B

    const int bh = blockIdx.y;
    const int rb = blockIdx.x;
    const int tid = threadIdx.x;
    const int lane = tid & 31;
    const int warp = tid >> 5;
    const int g = lane >> 2, t = lane & 3;

    // Q fragments: loaded once from gmem (read-once data).
    const float* qbase = g_q + ((size_t)bh * SEQ + rb * 64) * DKH;
    const int r0 = warp * 16 + g, r1 = r0 + 8;
    uint32_t qa[8][4];
#pragma unroll
    for (int ks = 0; ks < 8; ks++) {
        qa[ks][0] = f2tf32(qbase[r0 * DKH + ks * 8 + t]);
        qa[ks][1] = f2tf32(qbase[r1 * DKH + ks * 8 + t]);
        qa[ks][2] = f2tf32(qbase[r0 * DKH + ks * 8 + t + 4]);
        qa[ks][3] = f2tf32(qbase[r1 * DKH + ks * 8 + t + 4]);
    }

    float m0 = -INFINITY, m1 = -INFINITY, l0 = 0.0f, l1 = 0.0f;
    float o[8][4];
#pragma unroll
    for (int nt = 0; nt < 8; nt++)
#pragma unroll
        for (int j = 0; j < 4; j++) o[nt][j] = 0.0f;

    const float scale = 0.125f;
    const int row0 = rb * 64 + warp * 16 + g;
    const int tmax = 2 * rb + 1;

    const float* kbase = g_k + (size_t)bh * SEQ * DKH;
    const float* vbase = g_v + (size_t)bh * SEQ * DKH;

    // Preload tile 0 into buffer 0.
#pragma unroll
    for (int i = 0; i < 4; i++) {
        int e = tid + i * 128;
        int r = e >> 4, d4 = (e & 15) * 4;
        float4 kv = *(const float4*)(kbase + r * DKH + d4);
        float4 vv = *(const float4*)(vbase + r * DKH + d4);
        uint4 u;
        u.x = f2tf32(kv.x); u.y = f2tf32(kv.y); u.z = f2tf32(kv.z); u.w = f2tf32(kv.w);
        *(uint4*)&Ks[0][r * QPT + d4] = u;
        u.x = f2tf32(vv.x); u.y = f2tf32(vv.y); u.z = f2tf32(vv.z); u.w = f2tf32(vv.w);
        *(uint4*)&Vs[0][r * VPT + d4] = u;
    }
    __syncthreads();

    for (int tt = 0; tt <= tmax; tt++) {
        const int cur = tt & 1;

        // Prefetch next tile into registers (overlaps with compute below).
        float4 kr[4], vr[4];
        const bool have_next = (tt < tmax);
        if (have_next) {
            const float* kb = kbase + (size_t)(tt + 1) * 32 * DKH;
            const float* vb = vbase + (size_t)(tt + 1) * 32 * DKH;
#pragma unroll
            for (int i = 0; i < 4; i++) {
                int e = tid + i * 128;
                int r = e >> 4, d4 = (e & 15) * 4;
                kr[i] = *(const float4*)(kb + r * DKH + d4);
                vr[i] = *(const float4*)(vb + r * DKH + d4);
            }
        }

        // S = Q K^T
        float s_[4][4];
#pragma unroll
        for (int nt = 0; nt < 4; nt++)
#pragma unroll
            for (int j = 0; j < 4; j++) s_[nt][j] = 0.0f;

#pragma unroll
        for (int ks = 0; ks < 8; ks++) {
#pragma unroll
            for (int nt = 0; nt < 4; nt++) {
                uint32_t b[2];
                const uint32_t* kr_ = &Ks[cur][(nt * 8 + g) * QPT + ks * 8];
                b[0] = kr_[t];
                b[1] = kr_[t + 4];
                mma_tf32(s_[nt], qa[ks], b);
            }
        }

        // Online softmax (fp32)
        const bool masked = (tt >= 2 * rb);
        const int cbase = tt * 32 + 2 * t;
        float mx0 = -INFINITY, mx1 = -INFINITY;
#pragma unroll
        for (int nt = 0; nt < 4; nt++) {
#pragma unroll
            for (int j = 0; j < 4; j++) {
                float v = s_[nt][j] * scale;
                const int col = cbase + nt * 8 + (j & 1);
                const int row = row0 + (j >> 1) * 8;
                if (masked && col > row) v = -INFINITY;
                s_[nt][j] = v;
                if (j < 2) mx0 = fmaxf(mx0, v);
                else mx1 = fmaxf(mx1, v);
            }
        }
        mx0 = fmaxf(mx0, __shfl_xor_sync(0xFFFFFFFFu, mx0, 1));
        mx0 = fmaxf(mx0, __shfl_xor_sync(0xFFFFFFFFu, mx0, 2));
        mx1 = fmaxf(mx1, __shfl_xor_sync(0xFFFFFFFFu, mx1, 1));
        mx1 = fmaxf(mx1, __shfl_xor_sync(0xFFFFFFFFu, mx1, 2));

        const float mn0 = fmaxf(m0, mx0);
        const float mn1 = fmaxf(m1, mx1);
        const float scl0 = __expf(m0 - mn0);
        const float scl1 = __expf(m1 - mn1);

        float rs0 = 0.0f, rs1 = 0.0f;
#pragma unroll
        for (int nt = 0; nt < 4; nt++) {
            float p0 = __expf(s_[nt][0] - mn0);
            float p1 = __expf(s_[nt][1] - mn0);
            float p2 = __expf(s_[nt][2] - mn1);
            float p3 = __expf(s_[nt][3] - mn1);
            rs0 += p0 + p1;
            rs1 += p2 + p3;
            uint32_t* pr = &Ps[(warp * 16 + g) * PPT + nt * 8 + 2 * t];
            *(uint2*)pr = make_uint2(f2tf32(p0), f2tf32(p1));
            *(uint2*)(pr + 8 * PPT) = make_uint2(f2tf32(p2), f2tf32(p3));
        }
        rs0 += __shfl_xor_sync(0xFFFFFFFFu, rs0, 1);
        rs0 += __shfl_xor_sync(0xFFFFFFFFu, rs0, 2);
        rs1 += __shfl_xor_sync(0xFFFFFFFFu, rs1, 1);
        rs1 += __shfl_xor_sync(0xFFFFFFFFu, rs1, 2);

        l0 = l0 * scl0 + rs0;
        l1 = l1 * scl1 + rs1;
        m0 = mn0;
        m1 = mn1;

#pragma unroll
        for (int nt = 0; nt < 8; nt++) {
            o[nt][0] *= scl0;
            o[nt][1] *= scl0;
            o[nt][2] *= scl1;
            o[nt][3] *= scl1;
        }
        __syncwarp();

        // O += P V
#pragma unroll
        for (int ks = 0; ks < 4; ks++) {
            uint32_t a[4];
            const uint32_t* pr = &Ps[(warp * 16 + g) * PPT + ks * 8];
            a[0] = pr[t];
            a[1] = pr[8 * PPT + t];
            a[2] = pr[t + 4];
            a[3] = pr[8 * PPT + t + 4];
#pragma unroll
            for (int nt = 0; nt < 8; nt++) {
                uint32_t b[2];
                b[0] = Vs[cur][(ks * 8 + t) * VPT + nt * 8 + g];
                b[1] = Vs[cur][(ks * 8 + t + 4) * VPT + nt * 8 + g];
                mma_tf32(o[nt], a, b);
            }
        }
        __syncwarp();

        // Store prefetched tile into the other buffer; one sync per tile.
        if (have_next) {
            const int nxt = cur ^ 1;
#pragma unroll
            for (int i = 0; i < 4; i++) {
                int e = tid + i * 128;
                int r = e >> 4, d4 = (e & 15) * 4;
                uint4 u;
                u.x = f2tf32(kr[i].x); u.y = f2tf32(kr[i].y);
                u.z = f2tf32(kr[i].z); u.w = f2tf32(kr[i].w);
                *(uint4*)&Ks[nxt][r * QPT + d4] = u;
                u.x = f2tf32(vr[i].x); u.y = f2tf32(vr[i].y);
                u.z = f2tf32(vr[i].z); u.w = f2tf32(vr[i].w);
                *(uint4*)&Vs[nxt][r * VPT + d4] = u;
            }
        }
        __syncthreads();
    }

    // Write merged-head layout: (b, l, h*64+dk)
    const int bb = bh >> 4, hh = bh & 15;
    const float inv0 = 1.0f / l0;
    const float inv1 = 1.0f / l1;
    float* base0 = g_attn + ((size_t)(bb * SEQ + row0)) * DMODEL + hh * 64;
    float* base1 = base0 + (size_t)8 * DMODEL;
#pragma unroll
    for (int nt = 0; nt < 8; nt++) {
        const int c = nt * 8 + 2 * t;
        *(float2*)(base0 + c) = make_float2(o[nt][0] * inv0, o[nt][1] * inv0);
        *(float2*)(base1 + c) = make_float2(o[nt][2] * inv1, o[nt][3] * inv1);
    }
}

// ============================================================
// Launch: kernel launches ONLY
// ============================================================
extern "C" void kernel_launch(void* const* d_in, const int* in_sizes, int n_in,
                              void* d_out, int out_size) {
    const float* x = (const float*)d_in[0];
    const float* wq = (const float*)d_in[1];
    const float* wk = (const float*)d_in[2];
    const float* wv = (const float*)d_in[3];
    const float* wo = (const float*)d_in[4];
    float* out = (float*)d_out;

    dim3 gemm_grid(DMODEL / 128, MTOT / 128);  // (8, 32)
    qk3_gemm<0><<<gemm_grid, 256>>>(x, wq);            // Q (bf16x3 TC, fp32-accurate)
    qk3_gemm<1><<<gemm_grid, 256>>>(x, wk);            // K (bf16x3 TC, fp32-accurate)
    tf32_gemm<2><<<gemm_grid, 256>>>(x, wv, nullptr);  // V (tf32 TC)

    dim3 attn_grid(SEQ / 64, BHTOT);  // (32, 32)
    flash_attn_tc<<<attn_grid, 128>>>();

    tf32_gemm<3><<<gemm_grid, 256>>>(nullptr, wo, out);  // O (tf32 TC)
}